// round 9
// baseline (speedup 1.0000x reference)
#include <cuda_runtime.h>
#include <cuda_bf16.h>
#include <math_constants.h>
#include <cstdint>

// Problem constants
#define BATCH 2
#define TLEN 2048
#define DMODEL 1024
#define NHEADS 16
#define NGROUPS 4
#define DK 64
#define WINDOW 512
#define MTOK (BATCH * TLEN)   // 4096

// -------- scratch (static device globals; no runtime allocation) --------
__device__ float g_Q[MTOK * DMODEL];        // 16 MB
__device__ float g_K[MTOK * NGROUPS * DK];  // 4 MB
__device__ float g_V[MTOK * NGROUPS * DK];  // 4 MB
__device__ float g_ATT[MTOK * DMODEL];      // 16 MB

__device__ __forceinline__ uint32_t f2tf32(float f) {
    uint32_t u;
    asm volatile("cvt.rna.tf32.f32 %0, %1;" : "=r"(u) : "f"(f));
    return u;
}

__device__ __forceinline__ void mma_tf32(
    float& d0, float& d1, float& d2, float& d3,
    uint32_t a0, uint32_t a1, uint32_t a2, uint32_t a3,
    uint32_t b0, uint32_t b1)
{
    asm volatile(
        "mma.sync.aligned.m16n8k8.row.col.f32.tf32.tf32.f32 "
        "{%0,%1,%2,%3}, {%4,%5,%6,%7}, {%8,%9}, {%0,%1,%2,%3};\n"
        : "+f"(d0), "+f"(d1), "+f"(d2), "+f"(d3)
        : "r"(a0), "r"(a1), "r"(a2), "r"(a3), "r"(b0), "r"(b1));
}

__device__ __forceinline__ void cp_async16(uint32_t saddr, const void* gptr) {
    asm volatile("cp.async.cg.shared.global [%0], [%1], 16;"
                 :: "r"(saddr), "l"(gptr));
}
__device__ __forceinline__ void cp_commit() {
    asm volatile("cp.async.commit_group;");
}
__device__ __forceinline__ void cp_wait_all() {
    asm volatile("cp.async.wait_group 0;");
}

// =======================================================================
// TF32 GEMM, cp.async double-buffered:
// C[M,N] = A[M,K] @ B[N,K]^T ; BM=128 BN=64 BK=32; 8 warps, 32x32/warp.
// =======================================================================
#define BM 128
#define BN 64
#define BK 32
#define SPAD 36

__global__ __launch_bounds__(256) void gemm_tf32(
    const float* __restrict__ A,
    const float* __restrict__ B0, const float* __restrict__ B1,
    float* __restrict__ C0, float* __restrict__ C1,
    int M, int N, int K)
{
    extern __shared__ float gsm[];
    float (*As)[BM][SPAD] = (float(*)[BM][SPAD])gsm;
    float (*Bs)[BN][SPAD] = (float(*)[BN][SPAD])(gsm + 2 * BM * SPAD);

    const float* B = (blockIdx.z == 0) ? B0 : B1;
    float*       C = (blockIdx.z == 0) ? C0 : C1;

    const int tid  = threadIdx.x;
    const int warp = tid >> 5;
    const int lane = tid & 31;
    const int wm0  = (warp >> 1) * 32;
    const int wn0  = (warp & 1) * 32;
    const int m0   = blockIdx.y * BM;
    const int n0   = blockIdx.x * BN;

    const int r  = lane >> 2;
    const int cl = lane & 3;

    float c[2][4][4];
#pragma unroll
    for (int mt = 0; mt < 2; mt++)
#pragma unroll
        for (int nt = 0; nt < 4; nt++)
#pragma unroll
            for (int i = 0; i < 4; i++) c[mt][nt][i] = 0.f;

    const int lrow = tid >> 3;
    const int lcol = (tid & 7) * 4;

    auto issue = [&](int buf, int k0) {
#pragma unroll
        for (int p = 0; p < 4; p++)
            cp_async16((uint32_t)__cvta_generic_to_shared(&As[buf][p * 32 + lrow][lcol]),
                       A + (size_t)(m0 + p * 32 + lrow) * K + k0 + lcol);
#pragma unroll
        for (int p = 0; p < 2; p++)
            cp_async16((uint32_t)__cvta_generic_to_shared(&Bs[buf][p * 32 + lrow][lcol]),
                       B + (size_t)(n0 + p * 32 + lrow) * K + k0 + lcol);
        cp_commit();
    };

    issue(0, 0);
    int cur = 0;

    for (int k0 = 0; k0 < K; k0 += BK) {
        cp_wait_all();
        __syncthreads();
        if (k0 + BK < K) issue(cur ^ 1, k0 + BK);

#pragma unroll
        for (int kk = 0; kk < BK; kk += 8) {
            uint32_t af[2][4], bf[4][2];
#pragma unroll
            for (int mt = 0; mt < 2; mt++) {
                af[mt][0] = f2tf32(As[cur][wm0 + mt * 16 + r][kk + cl]);
                af[mt][1] = f2tf32(As[cur][wm0 + mt * 16 + r + 8][kk + cl]);
                af[mt][2] = f2tf32(As[cur][wm0 + mt * 16 + r][kk + cl + 4]);
                af[mt][3] = f2tf32(As[cur][wm0 + mt * 16 + r + 8][kk + cl + 4]);
            }
#pragma unroll
            for (int nt = 0; nt < 4; nt++) {
                bf[nt][0] = f2tf32(Bs[cur][wn0 + nt * 8 + r][kk + cl]);
                bf[nt][1] = f2tf32(Bs[cur][wn0 + nt * 8 + r][kk + cl + 4]);
            }
#pragma unroll
            for (int mt = 0; mt < 2; mt++)
#pragma unroll
                for (int nt = 0; nt < 4; nt++)
                    mma_tf32(c[mt][nt][0], c[mt][nt][1], c[mt][nt][2], c[mt][nt][3],
                             af[mt][0], af[mt][1], af[mt][2], af[mt][3],
                             bf[nt][0], bf[nt][1]);
        }
        cur ^= 1;
    }

#pragma unroll
    for (int mt = 0; mt < 2; mt++) {
#pragma unroll
        for (int nt = 0; nt < 4; nt++) {
            int row = m0 + wm0 + mt * 16 + r;
            int col = n0 + wn0 + nt * 8 + 2 * cl;
            *(float2*)(C + (size_t)row * N + col) =
                make_float2(c[mt][nt][0], c[mt][nt][1]);
            *(float2*)(C + (size_t)(row + 8) * N + col) =
                make_float2(c[mt][nt][2], c[mt][nt][3]);
        }
    }
}

// =======================================================================
// Fused RoPE for Q and K (interleaved pairs), in place.
// =======================================================================
#define NQ_ROPE (MTOK * NHEADS * 32)
#define NK_ROPE (MTOK * NGROUPS * 32)

__global__ void rope_all(float* __restrict__ Qx, float* __restrict__ Kx,
                         const int* __restrict__ pos)
{
    int idx = blockIdx.x * blockDim.x + threadIdx.x;
    float* X;
    int heads, local;
    if (idx < NQ_ROPE) { X = Qx; heads = NHEADS; local = idx; }
    else if (idx < NQ_ROPE + NK_ROPE) { X = Kx; heads = NGROUPS; local = idx - NQ_ROPE; }
    else return;

    int p = local & 31;
    int rest = local >> 5;
    int h = rest % heads;
    int m = rest / heads;
    int t = m & (TLEN - 1);

    float position = (float)pos[t];
    const float l2t = 13.287712379549449f;  // log2(10000)
    float inv = exp2f(-(float)p * (l2t / 32.0f));
    float ang = position * inv;
    float c, s;
    sincosf(ang, &s, &c);

    float* base = X + (size_t)m * (heads * DK) + h * DK + 2 * p;
    float x1 = base[0], x2 = base[1];
    base[0] = x1 * c - x2 * s;
    base[1] = x1 * s + x2 * c;
}

// =======================================================================
// Tensor-core flash attention v3: 128q x 64k tiles, FRAGMENT-LAYOUT smem.
// Q/K/V staged in mma-fragment order:
//   qfrag[warp][kk][lane] : uint4  (A-frag for QK^T)   -> 1 LDS.128
//   kfrag[kk][nt][lane]   : uint2  (B-frag for QK^T)   -> 1 LDS.64
//   vfrag[kk][nt][lane]   : uint2  (B-frag for P*V)    -> 1 LDS.64
// Softmax warp-local (m/l in registers), P via quad-shuffle C->A conv.
// smem = 32KB + 16KB + 16KB = 65536 B.
// =======================================================================
#define NEGBIG (-1e30f)
#define FULLM 0xffffffffu

__global__ __launch_bounds__(256) void attn_mma_kernel(
    const float* __restrict__ Q, const float* __restrict__ K,
    const float* __restrict__ V, float* __restrict__ O)
{
    extern __shared__ uint32_t asm_[];
    uint32_t* smq = asm_;             // 8192 words (8 warps * 8 kk * 32 lanes * 4)
    uint32_t* smk = asm_ + 8192;      // 4096 words (8 kk * 8 nt * 32 lanes * 2)
    uint32_t* smv = asm_ + 12288;     // 4096 words

    const int tid  = threadIdx.x;
    const int warp = tid >> 5;
    const int lane = tid & 31;
    const int r    = lane >> 2;   // 0..7
    const int cl   = lane & 3;    // 0..3

    const int q0 = blockIdx.x * 128;
    const int h  = blockIdx.y;
    const int b  = blockIdx.z;
    const int g  = h >> 2;

    const float* Qb = Q + ((size_t)(b * TLEN + q0)) * DMODEL + h * DK;
    const float* Kb = K + ((size_t)b * TLEN) * (NGROUPS * DK) + g * DK;
    const float* Vb = V + ((size_t)b * TLEN) * (NGROUPS * DK) + g * DK;

    // ---- stage Q (128x64, scaled by 1/8) into fragment layout ----
#pragma unroll
    for (int it = 0; it < 8; it++) {
        int f = tid + it * 256;
        int row = f >> 4;
        int d = (f & 15) * 4;
        float4 v = *(const float4*)(Qb + (size_t)row * DMODEL + d);
        int w = row >> 4, rloc = row & 15;
        int kk = d >> 3, c0 = d & 7;                 // c0 in {0,4}
        int slot = ((c0 >> 2) << 1) + (rloc >> 3);   // 0..3
        int lane0 = (rloc & 7) * 4;
        uint32_t* base = smq + ((w * 8 + kk) * 32) * 4 + slot;
        base[(lane0 + 0) * 4] = f2tf32(v.x * 0.125f);
        base[(lane0 + 1) * 4] = f2tf32(v.y * 0.125f);
        base[(lane0 + 2) * 4] = f2tf32(v.z * 0.125f);
        base[(lane0 + 3) * 4] = f2tf32(v.w * 0.125f);
    }

    const int row0 = warp * 16 + r;
    const int row1 = row0 + 8;
    const int i0 = q0 + row0;
    const int i1 = q0 + row1;

    float m0 = NEGBIG, l0 = 0.f;
    float m1 = NEGBIG, l1 = 0.f;
    float oc[8][4];
#pragma unroll
    for (int nt = 0; nt < 8; nt++)
#pragma unroll
        for (int i = 0; i < 4; i++) oc[nt][i] = 0.f;

    int jmin = q0 - WINDOW;
    if (jmin < 0) jmin = 0;

    const uint4* qf = (const uint4*)smq;
    const uint2* kf = (const uint2*)smk;
    const uint2* vf = (const uint2*)smv;

    for (int k0 = jmin; k0 < q0 + 128; k0 += 64) {
        __syncthreads();  // prior iteration's reads finished

        // ---- stage K tile -> kfrag: {K[8nt+r][8kk+cl], K[8nt+r][8kk+cl+4]} ----
#pragma unroll
        for (int it = 0; it < 4; it++) {
            int f = tid + it * 256;
            int j = f >> 4;
            int d = (f & 15) * 4;
            float4 v = *(const float4*)(Kb + (size_t)(k0 + j) * (NGROUPS * DK) + d);
            int nt = j >> 3, kk = d >> 3;
            int slot = (d & 7) >> 2;
            int lane0 = (j & 7) * 4;
            uint32_t* base = smk + ((kk * 8 + nt) * 32) * 2 + slot;
            base[(lane0 + 0) * 2] = f2tf32(v.x);
            base[(lane0 + 1) * 2] = f2tf32(v.y);
            base[(lane0 + 2) * 2] = f2tf32(v.z);
            base[(lane0 + 3) * 2] = f2tf32(v.w);
        }
        // ---- stage V tile -> vfrag: {V[8kk+cl][8nt+r], V[8kk+cl+4][8nt+r]} ----
#pragma unroll
        for (int it = 0; it < 4; it++) {
            int f = tid + it * 256;
            int j = f >> 4;
            int d = (f & 15) * 4;
            float4 v = *(const float4*)(Vb + (size_t)(k0 + j) * (NGROUPS * DK) + d);
            int kk = j >> 3;
            int cll = (j & 7) & 3;
            int slot = (j & 7) >> 2;
            int nt = d >> 3;
            int r0l = d & 7;
            uint32_t* base = smv + ((kk * 8 + nt) * 32) * 2 + slot;
            base[((r0l + 0) * 4 + cll) * 2] = f2tf32(v.x);
            base[((r0l + 1) * 4 + cll) * 2] = f2tf32(v.y);
            base[((r0l + 2) * 4 + cll) * 2] = f2tf32(v.z);
            base[((r0l + 3) * 4 + cll) * 2] = f2tf32(v.w);
        }
        __syncthreads();

        // ---- S = Q K^T: 8 kk x 8 nt, wide fragment loads ----
        float sc[8][4];
#pragma unroll
        for (int nt = 0; nt < 8; nt++)
#pragma unroll
            for (int i = 0; i < 4; i++) sc[nt][i] = 0.f;
#pragma unroll
        for (int kk = 0; kk < 8; kk++) {
            uint4 aq = qf[(warp * 8 + kk) * 32 + lane];   // LDS.128
#pragma unroll
            for (int nt = 0; nt < 8; nt++) {
                uint2 kb = kf[(kk * 8 + nt) * 32 + lane]; // LDS.64
                mma_tf32(sc[nt][0], sc[nt][1], sc[nt][2], sc[nt][3],
                         aq.x, aq.y, aq.z, aq.w, kb.x, kb.y);
            }
        }

        // ---- mask + row max (warp-local quad reduce) ----
        float rmax0 = NEGBIG, rmax1 = NEGBIG;
#pragma unroll
        for (int nt = 0; nt < 8; nt++) {
            int jc = k0 + nt * 8 + 2 * cl;
#pragma unroll
            for (int e = 0; e < 2; e++) {
                int j = jc + e;
                bool ok0 = (j <= i0) && (i0 - j <= WINDOW);
                bool ok1 = (j <= i1) && (i1 - j <= WINDOW);
                sc[nt][e]     = ok0 ? sc[nt][e]     : NEGBIG;
                sc[nt][e + 2] = ok1 ? sc[nt][e + 2] : NEGBIG;
                rmax0 = fmaxf(rmax0, sc[nt][e]);
                rmax1 = fmaxf(rmax1, sc[nt][e + 2]);
            }
        }
        rmax0 = fmaxf(rmax0, __shfl_xor_sync(FULLM, rmax0, 1));
        rmax0 = fmaxf(rmax0, __shfl_xor_sync(FULLM, rmax0, 2));
        rmax1 = fmaxf(rmax1, __shfl_xor_sync(FULLM, rmax1, 1));
        rmax1 = fmaxf(rmax1, __shfl_xor_sync(FULLM, rmax1, 2));

        float m_new0 = fmaxf(m0, rmax0);
        float m_new1 = fmaxf(m1, rmax1);
        float corr0 = __expf(m0 - m_new0);
        float corr1 = __expf(m1 - m_new1);

        // ---- exp + row sums ----
        float sum0 = 0.f, sum1 = 0.f;
#pragma unroll
        for (int nt = 0; nt < 8; nt++) {
            sc[nt][0] = __expf(sc[nt][0] - m_new0);
            sc[nt][1] = __expf(sc[nt][1] - m_new0);
            sc[nt][2] = __expf(sc[nt][2] - m_new1);
            sc[nt][3] = __expf(sc[nt][3] - m_new1);
            sum0 += sc[nt][0] + sc[nt][1];
            sum1 += sc[nt][2] + sc[nt][3];
        }
        sum0 += __shfl_xor_sync(FULLM, sum0, 1);
        sum0 += __shfl_xor_sync(FULLM, sum0, 2);
        sum1 += __shfl_xor_sync(FULLM, sum1, 1);
        sum1 += __shfl_xor_sync(FULLM, sum1, 2);

        l0 = l0 * corr0 + sum0;
        l1 = l1 * corr1 + sum1;
        m0 = m_new0;
        m1 = m_new1;

#pragma unroll
        for (int nt = 0; nt < 8; nt++) {
            oc[nt][0] *= corr0; oc[nt][1] *= corr0;
            oc[nt][2] *= corr1; oc[nt][3] *= corr1;
        }

        // ---- O += P V: C->A fragment conversion via quad shuffles ----
        const int qb = lane & ~3;
        const int s0l = qb + (cl >> 1);
        const int s1l = s0l + 2;
        const bool oddc = (cl & 1);
#pragma unroll
        for (int kk = 0; kk < 8; kk++) {
            float p0 = sc[kk][0], p1 = sc[kk][1];
            float p2 = sc[kk][2], p3 = sc[kk][3];
            float v00 = __shfl_sync(FULLM, p0, s0l);
            float v01 = __shfl_sync(FULLM, p1, s0l);
            float v20 = __shfl_sync(FULLM, p2, s0l);
            float v21 = __shfl_sync(FULLM, p3, s0l);
            float v00b = __shfl_sync(FULLM, p0, s1l);
            float v01b = __shfl_sync(FULLM, p1, s1l);
            float v20b = __shfl_sync(FULLM, p2, s1l);
            float v21b = __shfl_sync(FULLM, p3, s1l);
            uint32_t a0 = f2tf32(oddc ? v01  : v00);
            uint32_t a1 = f2tf32(oddc ? v21  : v20);
            uint32_t a2 = f2tf32(oddc ? v01b : v00b);
            uint32_t a3 = f2tf32(oddc ? v21b : v20b);
#pragma unroll
            for (int nt = 0; nt < 8; nt++) {
                uint2 vb = vf[(kk * 8 + nt) * 32 + lane]; // LDS.64
                mma_tf32(oc[nt][0], oc[nt][1], oc[nt][2], oc[nt][3],
                         a0, a1, a2, a3, vb.x, vb.y);
            }
        }
    }

    // ---- epilogue ----
    float inv0 = 1.0f / l0;
    float inv1 = 1.0f / l1;
    float* Ob0 = O + ((size_t)(b * TLEN + i0)) * DMODEL + h * DK;
    float* Ob1 = O + ((size_t)(b * TLEN + i1)) * DMODEL + h * DK;
#pragma unroll
    for (int nt = 0; nt < 8; nt++) {
        int dcol = nt * 8 + 2 * cl;
        *(float2*)(Ob0 + dcol) = make_float2(oc[nt][0] * inv0, oc[nt][1] * inv0);
        *(float2*)(Ob1 + dcol) = make_float2(oc[nt][2] * inv1, oc[nt][3] * inv1);
    }
}

// =======================================================================
// Host launcher
// =======================================================================
extern "C" void kernel_launch(void* const* d_in, const int* in_sizes, int n_in,
                              void* d_out, int out_size)
{
    const float* x  = (const float*)d_in[0];
    const float* WQ = (const float*)d_in[1];
    const float* WK = (const float*)d_in[2];
    const float* WV = (const float*)d_in[3];
    const float* WO = (const float*)d_in[4];
    const int* tpos = (const int*)d_in[5];
    float* out = (float*)d_out;

    float *Qp, *Kp, *Vp, *Ap;
    cudaGetSymbolAddress((void**)&Qp, g_Q);
    cudaGetSymbolAddress((void**)&Kp, g_K);
    cudaGetSymbolAddress((void**)&Vp, g_V);
    cudaGetSymbolAddress((void**)&Ap, g_ATT);

    const int gemm_smem = (2 * BM * SPAD + 2 * BN * SPAD) * 4;   // 55296 B
    const int attn_smem = 16384 * 4;                              // 65536 B
    static bool attr_done = false;
    if (!attr_done) {
        cudaFuncSetAttribute(gemm_tf32, cudaFuncAttributeMaxDynamicSharedMemorySize, gemm_smem);
        cudaFuncSetAttribute(attn_mma_kernel, cudaFuncAttributeMaxDynamicSharedMemorySize, attn_smem);
        attr_done = true;
    }

    // 1. Q projection
    gemm_tf32<<<dim3(DMODEL / BN, MTOK / BM, 1), 256, gemm_smem>>>(
        x, WQ, WQ, Qp, Qp, MTOK, DMODEL, DMODEL);
    // 1b. K and V projections fused
    gemm_tf32<<<dim3((NGROUPS * DK) / BN, MTOK / BM, 2), 256, gemm_smem>>>(
        x, WK, WV, Kp, Vp, MTOK, NGROUPS * DK, DMODEL);

    // 2. RoPE (Q and K in one launch)
    {
        int total = NQ_ROPE + NK_ROPE;
        rope_all<<<(total + 255) / 256, 256>>>(Qp, Kp, tpos);
    }

    // 3. Attention (128q x 64k tiles, fragment-layout smem)
    attn_mma_kernel<<<dim3(TLEN / 128, NHEADS, BATCH), 256, attn_smem>>>(Qp, Kp, Vp, Ap);

    // 4. Output projection
    gemm_tf32<<<dim3(DMODEL / BN, MTOK / BM, 1), 256, gemm_smem>>>(
        Ap, WO, WO, out, out, MTOK, DMODEL, DMODEL);
}

// round 11
// speedup vs baseline: 1.2199x; 1.2199x over previous
#include <cuda_runtime.h>
#include <cuda_bf16.h>
#include <math_constants.h>
#include <cstdint>

// Problem constants
#define BATCH 2
#define TLEN 2048
#define DMODEL 1024
#define NHEADS 16
#define NGROUPS 4
#define DK 64
#define WINDOW 512
#define MTOK (BATCH * TLEN)   // 4096

// -------- scratch (static device globals; no runtime allocation) --------
__device__ float g_Q[MTOK * DMODEL];        // 16 MB
__device__ float g_K[MTOK * NGROUPS * DK];  // 4 MB
__device__ float g_V[MTOK * NGROUPS * DK];  // 4 MB
__device__ float g_ATT[MTOK * DMODEL];      // 16 MB

__device__ __forceinline__ uint32_t f2tf32(float f) {
    uint32_t u;
    asm volatile("cvt.rna.tf32.f32 %0, %1;" : "=r"(u) : "f"(f));
    return u;
}

__device__ __forceinline__ void mma_tf32(
    float& d0, float& d1, float& d2, float& d3,
    uint32_t a0, uint32_t a1, uint32_t a2, uint32_t a3,
    uint32_t b0, uint32_t b1)
{
    asm volatile(
        "mma.sync.aligned.m16n8k8.row.col.f32.tf32.tf32.f32 "
        "{%0,%1,%2,%3}, {%4,%5,%6,%7}, {%8,%9}, {%0,%1,%2,%3};\n"
        : "+f"(d0), "+f"(d1), "+f"(d2), "+f"(d3)
        : "r"(a0), "r"(a1), "r"(a2), "r"(a3), "r"(b0), "r"(b1));
}

__device__ __forceinline__ void cp_async16(uint32_t saddr, const void* gptr) {
    asm volatile("cp.async.cg.shared.global [%0], [%1], 16;"
                 :: "r"(saddr), "l"(gptr));
}
__device__ __forceinline__ void cp_commit() {
    asm volatile("cp.async.commit_group;");
}
__device__ __forceinline__ void cp_wait_all() {
    asm volatile("cp.async.wait_group 0;");
}

// =======================================================================
// TF32 GEMM v2, cp.async double-buffered, WIDE tile:
// C[M,N] = A[M,K] @ B[N,K]^T ; BM=128 BN=128 BK=32; 8 warps (4m x 2n),
// warp tile 32x64 = 2 m-tiles x 8 n-tiles of m16n8k8.
// blockIdx.z selects (B,C) pair -> fuses K/V projections in one launch.
// =======================================================================
#define BM 128
#define BN 128
#define BK 32
#define SPAD 36

__global__ __launch_bounds__(256) void gemm_tf32(
    const float* __restrict__ A,
    const float* __restrict__ B0, const float* __restrict__ B1,
    float* __restrict__ C0, float* __restrict__ C1,
    int M, int N, int K)
{
    extern __shared__ float gsm[];
    float (*As)[BM][SPAD] = (float(*)[BM][SPAD])gsm;                   // 2 bufs
    float (*Bs)[BN][SPAD] = (float(*)[BN][SPAD])(gsm + 2 * BM * SPAD); // 2 bufs

    const float* B = (blockIdx.z == 0) ? B0 : B1;
    float*       C = (blockIdx.z == 0) ? C0 : C1;

    const int tid  = threadIdx.x;
    const int warp = tid >> 5;
    const int lane = tid & 31;
    const int wm0  = (warp >> 1) * 32;   // 0,32,64,96
    const int wn0  = (warp & 1) * 64;    // 0,64
    const int m0   = blockIdx.y * BM;
    const int n0   = blockIdx.x * BN;

    const int r  = lane >> 2;
    const int cl = lane & 3;

    float c[2][8][4];
#pragma unroll
    for (int mt = 0; mt < 2; mt++)
#pragma unroll
        for (int nt = 0; nt < 8; nt++)
#pragma unroll
            for (int i = 0; i < 4; i++) c[mt][nt][i] = 0.f;

    const int lrow = tid >> 3;        // 0..31
    const int lcol = (tid & 7) * 4;   // 0..28

    auto issue = [&](int buf, int k0) {
#pragma unroll
        for (int p = 0; p < 4; p++)
            cp_async16((uint32_t)__cvta_generic_to_shared(&As[buf][p * 32 + lrow][lcol]),
                       A + (size_t)(m0 + p * 32 + lrow) * K + k0 + lcol);
#pragma unroll
        for (int p = 0; p < 4; p++)
            cp_async16((uint32_t)__cvta_generic_to_shared(&Bs[buf][p * 32 + lrow][lcol]),
                       B + (size_t)(n0 + p * 32 + lrow) * K + k0 + lcol);
        cp_commit();
    };

    issue(0, 0);
    int cur = 0;

    for (int k0 = 0; k0 < K; k0 += BK) {
        cp_wait_all();
        __syncthreads();
        if (k0 + BK < K) issue(cur ^ 1, k0 + BK);

#pragma unroll
        for (int kk = 0; kk < BK; kk += 8) {
            uint32_t af[2][4], bf[8][2];
#pragma unroll
            for (int mt = 0; mt < 2; mt++) {
                af[mt][0] = f2tf32(As[cur][wm0 + mt * 16 + r][kk + cl]);
                af[mt][1] = f2tf32(As[cur][wm0 + mt * 16 + r + 8][kk + cl]);
                af[mt][2] = f2tf32(As[cur][wm0 + mt * 16 + r][kk + cl + 4]);
                af[mt][3] = f2tf32(As[cur][wm0 + mt * 16 + r + 8][kk + cl + 4]);
            }
#pragma unroll
            for (int nt = 0; nt < 8; nt++) {
                bf[nt][0] = f2tf32(Bs[cur][wn0 + nt * 8 + r][kk + cl]);
                bf[nt][1] = f2tf32(Bs[cur][wn0 + nt * 8 + r][kk + cl + 4]);
            }
#pragma unroll
            for (int mt = 0; mt < 2; mt++)
#pragma unroll
                for (int nt = 0; nt < 8; nt++)
                    mma_tf32(c[mt][nt][0], c[mt][nt][1], c[mt][nt][2], c[mt][nt][3],
                             af[mt][0], af[mt][1], af[mt][2], af[mt][3],
                             bf[nt][0], bf[nt][1]);
        }
        cur ^= 1;
    }

#pragma unroll
    for (int mt = 0; mt < 2; mt++) {
#pragma unroll
        for (int nt = 0; nt < 8; nt++) {
            int row = m0 + wm0 + mt * 16 + r;
            int col = n0 + wn0 + nt * 8 + 2 * cl;
            *(float2*)(C + (size_t)row * N + col) =
                make_float2(c[mt][nt][0], c[mt][nt][1]);
            *(float2*)(C + (size_t)(row + 8) * N + col) =
                make_float2(c[mt][nt][2], c[mt][nt][3]);
        }
    }
}

// =======================================================================
// Fused RoPE for Q and K (interleaved pairs), in place.
// =======================================================================
#define NQ_ROPE (MTOK * NHEADS * 32)
#define NK_ROPE (MTOK * NGROUPS * 32)

__global__ void rope_all(float* __restrict__ Qx, float* __restrict__ Kx,
                         const int* __restrict__ pos)
{
    int idx = blockIdx.x * blockDim.x + threadIdx.x;
    float* X;
    int heads, local;
    if (idx < NQ_ROPE) { X = Qx; heads = NHEADS; local = idx; }
    else if (idx < NQ_ROPE + NK_ROPE) { X = Kx; heads = NGROUPS; local = idx - NQ_ROPE; }
    else return;

    int p = local & 31;
    int rest = local >> 5;
    int h = rest % heads;
    int m = rest / heads;
    int t = m & (TLEN - 1);

    float position = (float)pos[t];
    const float l2t = 13.287712379549449f;  // log2(10000)
    float inv = exp2f(-(float)p * (l2t / 32.0f));
    float ang = position * inv;
    float c, s;
    sincosf(ang, &s, &c);

    float* base = X + (size_t)m * (heads * DK) + h * DK + 2 * p;
    float x1 = base[0], x2 = base[1];
    base[0] = x1 * c - x2 * s;
    base[1] = x1 * s + x2 * c;
}

// =======================================================================
// Tensor-core flash attention (R6 version, measured 108.6us):
// 128q x 64k tiles; warp owns 16 rows; softmax warp-local; P via
// quad-shuffle C->A conversion. Row-major smem tiles (conflict-free STS).
// =======================================================================
#define NEGBIG (-1e30f)
#define FULLM 0xffffffffu

__global__ __launch_bounds__(256) void attn_mma_kernel(
    const float* __restrict__ Q, const float* __restrict__ K,
    const float* __restrict__ V, float* __restrict__ O)
{
    extern __shared__ uint32_t asm_[];
    uint32_t (*qs)[68]  = (uint32_t(*)[68])asm_;
    uint32_t (*ks)[68]  = (uint32_t(*)[68])(asm_ + 128 * 68);
    uint32_t (*vts)[68] = (uint32_t(*)[68])(asm_ + 128 * 68 + 64 * 68);

    const int tid  = threadIdx.x;
    const int warp = tid >> 5;
    const int lane = tid & 31;
    const int r    = lane >> 2;   // 0..7
    const int cl   = lane & 3;    // 0..3

    const int q0 = blockIdx.x * 128;
    const int h  = blockIdx.y;
    const int b  = blockIdx.z;
    const int g  = h >> 2;

    const float* Qb = Q + ((size_t)(b * TLEN + q0)) * DMODEL + h * DK;
    const float* Kb = K + ((size_t)b * TLEN) * (NGROUPS * DK) + g * DK;
    const float* Vb = V + ((size_t)b * TLEN) * (NGROUPS * DK) + g * DK;

    // ---- stage Q (128x64, scaled by 1/8, tf32) ----
#pragma unroll
    for (int it = 0; it < 8; it++) {
        int f = tid + it * 256;
        int row = f >> 4;
        int d = (f & 15) * 4;
        float4 v = *(const float4*)(Qb + (size_t)row * DMODEL + d);
        uint4 t = make_uint4(f2tf32(v.x * 0.125f), f2tf32(v.y * 0.125f),
                             f2tf32(v.z * 0.125f), f2tf32(v.w * 0.125f));
        *(uint4*)&qs[row][d] = t;
    }

    const int row0 = warp * 16 + r;
    const int row1 = row0 + 8;
    const int i0 = q0 + row0;
    const int i1 = q0 + row1;

    float m0 = NEGBIG, l0 = 0.f;
    float m1 = NEGBIG, l1 = 0.f;
    float oc[8][4];
#pragma unroll
    for (int nt = 0; nt < 8; nt++)
#pragma unroll
        for (int i = 0; i < 4; i++) oc[nt][i] = 0.f;

    int jmin = q0 - WINDOW;
    if (jmin < 0) jmin = 0;

    for (int k0 = jmin; k0 < q0 + 128; k0 += 64) {
        __syncthreads();  // prior iteration's reads of ks/vts finished

        // ---- stage K tile [64 keys][64 d] ----
#pragma unroll
        for (int it = 0; it < 4; it++) {
            int f = tid + it * 256;
            int jj = f >> 4;
            int d = (f & 15) * 4;
            float4 v = *(const float4*)(Kb + (size_t)(k0 + jj) * (NGROUPS * DK) + d);
            uint4 t = make_uint4(f2tf32(v.x), f2tf32(v.y), f2tf32(v.z), f2tf32(v.w));
            *(uint4*)&ks[jj][d] = t;
        }
        // ---- stage V^T tile [64 d][64 keys] ----
#pragma unroll
        for (int it = 0; it < 4; it++) {
            int f = tid + it * 256;
            int jj = f & 63;
            int d = (f >> 6) * 4;
            float4 v = *(const float4*)(Vb + (size_t)(k0 + jj) * (NGROUPS * DK) + d);
            vts[d + 0][jj] = f2tf32(v.x);
            vts[d + 1][jj] = f2tf32(v.y);
            vts[d + 2][jj] = f2tf32(v.z);
            vts[d + 3][jj] = f2tf32(v.w);
        }
        __syncthreads();

        // ---- S = Q K^T: warp rows x 64 keys (8 n-tiles, 8 k-steps) ----
        float sc[8][4];
#pragma unroll
        for (int nt = 0; nt < 8; nt++)
#pragma unroll
            for (int i = 0; i < 4; i++) sc[nt][i] = 0.f;
#pragma unroll
        for (int kk = 0; kk < 8; kk++) {
            uint32_t a0 = qs[row0][kk * 8 + cl];
            uint32_t a1 = qs[row1][kk * 8 + cl];
            uint32_t a2 = qs[row0][kk * 8 + cl + 4];
            uint32_t a3 = qs[row1][kk * 8 + cl + 4];
#pragma unroll
            for (int nt = 0; nt < 8; nt++) {
                uint32_t b0 = ks[nt * 8 + r][kk * 8 + cl];
                uint32_t b1 = ks[nt * 8 + r][kk * 8 + cl + 4];
                mma_tf32(sc[nt][0], sc[nt][1], sc[nt][2], sc[nt][3],
                         a0, a1, a2, a3, b0, b1);
            }
        }

        // ---- mask + row max (warp-local, quad reduce) ----
        float rmax0 = NEGBIG, rmax1 = NEGBIG;
#pragma unroll
        for (int nt = 0; nt < 8; nt++) {
            int jc = k0 + nt * 8 + 2 * cl;
#pragma unroll
            for (int e = 0; e < 2; e++) {
                int j = jc + e;
                bool ok0 = (j <= i0) && (i0 - j <= WINDOW);
                bool ok1 = (j <= i1) && (i1 - j <= WINDOW);
                sc[nt][e]     = ok0 ? sc[nt][e]     : NEGBIG;
                sc[nt][e + 2] = ok1 ? sc[nt][e + 2] : NEGBIG;
                rmax0 = fmaxf(rmax0, sc[nt][e]);
                rmax1 = fmaxf(rmax1, sc[nt][e + 2]);
            }
        }
        rmax0 = fmaxf(rmax0, __shfl_xor_sync(FULLM, rmax0, 1));
        rmax0 = fmaxf(rmax0, __shfl_xor_sync(FULLM, rmax0, 2));
        rmax1 = fmaxf(rmax1, __shfl_xor_sync(FULLM, rmax1, 1));
        rmax1 = fmaxf(rmax1, __shfl_xor_sync(FULLM, rmax1, 2));

        float m_new0 = fmaxf(m0, rmax0);
        float m_new1 = fmaxf(m1, rmax1);
        float corr0 = __expf(m0 - m_new0);
        float corr1 = __expf(m1 - m_new1);

        // ---- exp + row sums ----
        float sum0 = 0.f, sum1 = 0.f;
#pragma unroll
        for (int nt = 0; nt < 8; nt++) {
            sc[nt][0] = __expf(sc[nt][0] - m_new0);
            sc[nt][1] = __expf(sc[nt][1] - m_new0);
            sc[nt][2] = __expf(sc[nt][2] - m_new1);
            sc[nt][3] = __expf(sc[nt][3] - m_new1);
            sum0 += sc[nt][0] + sc[nt][1];
            sum1 += sc[nt][2] + sc[nt][3];
        }
        sum0 += __shfl_xor_sync(FULLM, sum0, 1);
        sum0 += __shfl_xor_sync(FULLM, sum0, 2);
        sum1 += __shfl_xor_sync(FULLM, sum1, 1);
        sum1 += __shfl_xor_sync(FULLM, sum1, 2);

        l0 = l0 * corr0 + sum0;
        l1 = l1 * corr1 + sum1;
        m0 = m_new0;
        m1 = m_new1;

        // ---- rescale O accumulators ----
#pragma unroll
        for (int nt = 0; nt < 8; nt++) {
            oc[nt][0] *= corr0; oc[nt][1] *= corr0;
            oc[nt][2] *= corr1; oc[nt][3] *= corr1;
        }

        // ---- O += P V: convert C-frag P -> A-frag via quad shuffles ----
        const int qb = lane & ~3;       // quad base lane
        const int s0l = qb + (cl >> 1); // src lane for cols cl
        const int s1l = s0l + 2;        // src lane for cols cl+4
        const bool oddc = (cl & 1);
#pragma unroll
        for (int kk = 0; kk < 8; kk++) {
            float p0 = sc[kk][0], p1 = sc[kk][1];
            float p2 = sc[kk][2], p3 = sc[kk][3];
            float v00 = __shfl_sync(FULLM, p0, s0l);
            float v01 = __shfl_sync(FULLM, p1, s0l);
            float v20 = __shfl_sync(FULLM, p2, s0l);
            float v21 = __shfl_sync(FULLM, p3, s0l);
            float v00b = __shfl_sync(FULLM, p0, s1l);
            float v01b = __shfl_sync(FULLM, p1, s1l);
            float v20b = __shfl_sync(FULLM, p2, s1l);
            float v21b = __shfl_sync(FULLM, p3, s1l);
            uint32_t a0 = f2tf32(oddc ? v01  : v00);   // P[row0][cl]
            uint32_t a1 = f2tf32(oddc ? v21  : v20);   // P[row1][cl]
            uint32_t a2 = f2tf32(oddc ? v01b : v00b);  // P[row0][cl+4]
            uint32_t a3 = f2tf32(oddc ? v21b : v20b);  // P[row1][cl+4]
#pragma unroll
            for (int nt = 0; nt < 8; nt++) {
                uint32_t b0 = vts[nt * 8 + r][kk * 8 + cl];
                uint32_t b1 = vts[nt * 8 + r][kk * 8 + cl + 4];
                mma_tf32(oc[nt][0], oc[nt][1], oc[nt][2], oc[nt][3],
                         a0, a1, a2, a3, b0, b1);
            }
        }
    }

    // ---- epilogue ----
    float inv0 = 1.0f / l0;
    float inv1 = 1.0f / l1;
    float* Ob0 = O + ((size_t)(b * TLEN + i0)) * DMODEL + h * DK;
    float* Ob1 = O + ((size_t)(b * TLEN + i1)) * DMODEL + h * DK;
#pragma unroll
    for (int nt = 0; nt < 8; nt++) {
        int dcol = nt * 8 + 2 * cl;
        *(float2*)(Ob0 + dcol) = make_float2(oc[nt][0] * inv0, oc[nt][1] * inv0);
        *(float2*)(Ob1 + dcol) = make_float2(oc[nt][2] * inv1, oc[nt][3] * inv1);
    }
}

// =======================================================================
// Host launcher
// =======================================================================
extern "C" void kernel_launch(void* const* d_in, const int* in_sizes, int n_in,
                              void* d_out, int out_size)
{
    const float* x  = (const float*)d_in[0];
    const float* WQ = (const float*)d_in[1];
    const float* WK = (const float*)d_in[2];
    const float* WV = (const float*)d_in[3];
    const float* WO = (const float*)d_in[4];
    const int* tpos = (const int*)d_in[5];
    float* out = (float*)d_out;

    float *Qp, *Kp, *Vp, *Ap;
    cudaGetSymbolAddress((void**)&Qp, g_Q);
    cudaGetSymbolAddress((void**)&Kp, g_K);
    cudaGetSymbolAddress((void**)&Vp, g_V);
    cudaGetSymbolAddress((void**)&Ap, g_ATT);

    const int gemm_smem = (2 * BM * SPAD + 2 * BN * SPAD) * 4;   // 73728 B
    const int attn_smem = (128 * 68 + 64 * 68 + 64 * 68) * 4;    // 69632 B
    static bool attr_done = false;
    if (!attr_done) {
        cudaFuncSetAttribute(gemm_tf32, cudaFuncAttributeMaxDynamicSharedMemorySize, gemm_smem);
        cudaFuncSetAttribute(attn_mma_kernel, cudaFuncAttributeMaxDynamicSharedMemorySize, attn_smem);
        attr_done = true;
    }

    // 1. Q projection (BN=128 wide tiles)
    gemm_tf32<<<dim3(DMODEL / BN, MTOK / BM, 1), 256, gemm_smem>>>(
        x, WQ, WQ, Qp, Qp, MTOK, DMODEL, DMODEL);
    // 1b. K and V projections fused
    gemm_tf32<<<dim3((NGROUPS * DK) / BN, MTOK / BM, 2), 256, gemm_smem>>>(
        x, WK, WV, Kp, Vp, MTOK, NGROUPS * DK, DMODEL);

    // 2. RoPE (Q and K in one launch)
    {
        int total = NQ_ROPE + NK_ROPE;
        rope_all<<<(total + 255) / 256, 256>>>(Qp, Kp, tpos);
    }

    // 3. Attention (R6 kernel: 128q x 64k tiles)
    attn_mma_kernel<<<dim3(TLEN / 128, NHEADS, BATCH), 256, attn_smem>>>(Qp, Kp, Vp, Ap);

    // 4. Output projection
    gemm_tf32<<<dim3(DMODEL / BN, MTOK / BM, 1), 256, gemm_smem>>>(
        Ap, WO, WO, out, out, MTOK, DMODEL, DMODEL);
}

// round 12
// speedup vs baseline: 1.2559x; 1.0295x over previous
#include <cuda_runtime.h>
#include <cuda_bf16.h>
#include <math_constants.h>
#include <cstdint>

// Problem constants
#define BATCH 2
#define TLEN 2048
#define DMODEL 1024
#define NHEADS 16
#define NGROUPS 4
#define DK 64
#define WINDOW 512
#define MTOK (BATCH * TLEN)   // 4096

// -------- scratch (static device globals; no runtime allocation) --------
__device__ float g_Q[MTOK * DMODEL];        // 16 MB
__device__ float g_K[MTOK * NGROUPS * DK];  // 4 MB
__device__ float g_V[MTOK * NGROUPS * DK];  // 4 MB
__device__ float g_ATT[MTOK * DMODEL];      // 16 MB

__device__ __forceinline__ uint32_t f2tf32(float f) {
    uint32_t u;
    asm volatile("cvt.rna.tf32.f32 %0, %1;" : "=r"(u) : "f"(f));
    return u;
}

__device__ __forceinline__ void mma_tf32(
    float& d0, float& d1, float& d2, float& d3,
    uint32_t a0, uint32_t a1, uint32_t a2, uint32_t a3,
    uint32_t b0, uint32_t b1)
{
    asm volatile(
        "mma.sync.aligned.m16n8k8.row.col.f32.tf32.tf32.f32 "
        "{%0,%1,%2,%3}, {%4,%5,%6,%7}, {%8,%9}, {%0,%1,%2,%3};\n"
        : "+f"(d0), "+f"(d1), "+f"(d2), "+f"(d3)
        : "r"(a0), "r"(a1), "r"(a2), "r"(a3), "r"(b0), "r"(b1));
}

__device__ __forceinline__ void cp_async16(uint32_t saddr, const void* gptr) {
    asm volatile("cp.async.cg.shared.global [%0], [%1], 16;"
                 :: "r"(saddr), "l"(gptr));
}
__device__ __forceinline__ void cp_commit() {
    asm volatile("cp.async.commit_group;");
}
__device__ __forceinline__ void cp_wait_all() {
    asm volatile("cp.async.wait_group 0;");
}

// =======================================================================
// TF32 GEMM, cp.async double-buffered, WIDE tile:
// C[M,N] = A[M,K] @ B[N,K]^T ; BM=128 BN=128 BK=32; 8 warps (4m x 2n),
// warp tile 32x64 = 2 m-tiles x 8 n-tiles of m16n8k8.
// =======================================================================
#define BM 128
#define BN 128
#define BK 32
#define SPAD 36

__global__ __launch_bounds__(256, 2) void gemm_tf32(
    const float* __restrict__ A,
    const float* __restrict__ B0, const float* __restrict__ B1,
    float* __restrict__ C0, float* __restrict__ C1,
    int M, int N, int K)
{
    extern __shared__ float gsm[];
    float (*As)[BM][SPAD] = (float(*)[BM][SPAD])gsm;                   // 2 bufs
    float (*Bs)[BN][SPAD] = (float(*)[BN][SPAD])(gsm + 2 * BM * SPAD); // 2 bufs

    const float* B = (blockIdx.z == 0) ? B0 : B1;
    float*       C = (blockIdx.z == 0) ? C0 : C1;

    const int tid  = threadIdx.x;
    const int warp = tid >> 5;
    const int lane = tid & 31;
    const int wm0  = (warp >> 1) * 32;   // 0,32,64,96
    const int wn0  = (warp & 1) * 64;    // 0,64
    const int m0   = blockIdx.y * BM;
    const int n0   = blockIdx.x * BN;

    const int r  = lane >> 2;
    const int cl = lane & 3;

    float c[2][8][4];
#pragma unroll
    for (int mt = 0; mt < 2; mt++)
#pragma unroll
        for (int nt = 0; nt < 8; nt++)
#pragma unroll
            for (int i = 0; i < 4; i++) c[mt][nt][i] = 0.f;

    const int lrow = tid >> 3;        // 0..31
    const int lcol = (tid & 7) * 4;   // 0..28

    auto issue = [&](int buf, int k0) {
#pragma unroll
        for (int p = 0; p < 4; p++)
            cp_async16((uint32_t)__cvta_generic_to_shared(&As[buf][p * 32 + lrow][lcol]),
                       A + (size_t)(m0 + p * 32 + lrow) * K + k0 + lcol);
#pragma unroll
        for (int p = 0; p < 4; p++)
            cp_async16((uint32_t)__cvta_generic_to_shared(&Bs[buf][p * 32 + lrow][lcol]),
                       B + (size_t)(n0 + p * 32 + lrow) * K + k0 + lcol);
        cp_commit();
    };

    issue(0, 0);
    int cur = 0;

    for (int k0 = 0; k0 < K; k0 += BK) {
        cp_wait_all();
        __syncthreads();
        if (k0 + BK < K) issue(cur ^ 1, k0 + BK);

#pragma unroll
        for (int kk = 0; kk < BK; kk += 8) {
            uint32_t af[2][4], bf[8][2];
#pragma unroll
            for (int mt = 0; mt < 2; mt++) {
                af[mt][0] = f2tf32(As[cur][wm0 + mt * 16 + r][kk + cl]);
                af[mt][1] = f2tf32(As[cur][wm0 + mt * 16 + r + 8][kk + cl]);
                af[mt][2] = f2tf32(As[cur][wm0 + mt * 16 + r][kk + cl + 4]);
                af[mt][3] = f2tf32(As[cur][wm0 + mt * 16 + r + 8][kk + cl + 4]);
            }
#pragma unroll
            for (int nt = 0; nt < 8; nt++) {
                bf[nt][0] = f2tf32(Bs[cur][wn0 + nt * 8 + r][kk + cl]);
                bf[nt][1] = f2tf32(Bs[cur][wn0 + nt * 8 + r][kk + cl + 4]);
            }
#pragma unroll
            for (int mt = 0; mt < 2; mt++)
#pragma unroll
                for (int nt = 0; nt < 8; nt++)
                    mma_tf32(c[mt][nt][0], c[mt][nt][1], c[mt][nt][2], c[mt][nt][3],
                             af[mt][0], af[mt][1], af[mt][2], af[mt][3],
                             bf[nt][0], bf[nt][1]);
        }
        cur ^= 1;
    }

#pragma unroll
    for (int mt = 0; mt < 2; mt++) {
#pragma unroll
        for (int nt = 0; nt < 8; nt++) {
            int row = m0 + wm0 + mt * 16 + r;
            int col = n0 + wn0 + nt * 8 + 2 * cl;
            *(float2*)(C + (size_t)row * N + col) =
                make_float2(c[mt][nt][0], c[mt][nt][1]);
            *(float2*)(C + (size_t)(row + 8) * N + col) =
                make_float2(c[mt][nt][2], c[mt][nt][3]);
        }
    }
}

// =======================================================================
// Fused RoPE for Q and K (interleaved pairs), in place.
// =======================================================================
#define NQ_ROPE (MTOK * NHEADS * 32)
#define NK_ROPE (MTOK * NGROUPS * 32)

__global__ void rope_all(float* __restrict__ Qx, float* __restrict__ Kx,
                         const int* __restrict__ pos)
{
    int idx = blockIdx.x * blockDim.x + threadIdx.x;
    float* X;
    int heads, local;
    if (idx < NQ_ROPE) { X = Qx; heads = NHEADS; local = idx; }
    else if (idx < NQ_ROPE + NK_ROPE) { X = Kx; heads = NGROUPS; local = idx - NQ_ROPE; }
    else return;

    int p = local & 31;
    int rest = local >> 5;
    int h = rest % heads;
    int m = rest / heads;
    int t = m & (TLEN - 1);

    float position = (float)pos[t];
    const float l2t = 13.287712379549449f;  // log2(10000)
    float inv = exp2f(-(float)p * (l2t / 32.0f));
    float ang = position * inv;
    float c, s;
    sincosf(ang, &s, &c);

    float* base = X + (size_t)m * (heads * DK) + h * DK + 2 * p;
    float x1 = base[0], x2 = base[1];
    base[0] = x1 * c - x2 * s;
    base[1] = x1 * s + x2 * c;
}

// =======================================================================
// Tensor-core flash attention v4: 128q x 64k tiles, DOUBLE-BUFFERED K/V,
// one __syncthreads per key tile; warp owns 16 rows; softmax warp-local;
// P via quad-shuffle C->A conversion.
// smem: qs[128][68] + 2 x (ks[64][68] + vts[64][68]) = 104448 B.
// __launch_bounds__(256,2) -> 2 CTAs/SM (occupancy was the R11 limiter).
// =======================================================================
#define NEGBIG (-1e30f)
#define FULLM 0xffffffffu

__global__ __launch_bounds__(256, 2) void attn_mma_kernel(
    const float* __restrict__ Q, const float* __restrict__ K,
    const float* __restrict__ V, float* __restrict__ O)
{
    extern __shared__ uint32_t asm_[];
    uint32_t (*qs)[68] = (uint32_t(*)[68])asm_;                       // 128 rows
    // double-buffered K and V^T tiles
    uint32_t (*ks)[64][68]  = (uint32_t(*)[64][68])(asm_ + 128 * 68);
    uint32_t (*vts)[64][68] = (uint32_t(*)[64][68])(asm_ + 128 * 68 + 2 * 64 * 68);

    const int tid  = threadIdx.x;
    const int warp = tid >> 5;
    const int lane = tid & 31;
    const int r    = lane >> 2;   // 0..7
    const int cl   = lane & 3;    // 0..3

    const int q0 = blockIdx.x * 128;
    const int h  = blockIdx.y;
    const int b  = blockIdx.z;
    const int g  = h >> 2;

    const float* Qb = Q + ((size_t)(b * TLEN + q0)) * DMODEL + h * DK;
    const float* Kb = K + ((size_t)b * TLEN) * (NGROUPS * DK) + g * DK;
    const float* Vb = V + ((size_t)b * TLEN) * (NGROUPS * DK) + g * DK;

    // ---- stage Q (128x64, scaled by 1/8, tf32) ----
#pragma unroll
    for (int it = 0; it < 8; it++) {
        int f = tid + it * 256;
        int row = f >> 4;
        int d = (f & 15) * 4;
        float4 v = *(const float4*)(Qb + (size_t)row * DMODEL + d);
        uint4 t = make_uint4(f2tf32(v.x * 0.125f), f2tf32(v.y * 0.125f),
                             f2tf32(v.z * 0.125f), f2tf32(v.w * 0.125f));
        *(uint4*)&qs[row][d] = t;
    }

    // K/V tile staging helper
    auto stage_kv = [&](int buf, int k0) {
#pragma unroll
        for (int it = 0; it < 4; it++) {
            int f = tid + it * 256;
            int jj = f >> 4;
            int d = (f & 15) * 4;
            float4 v = *(const float4*)(Kb + (size_t)(k0 + jj) * (NGROUPS * DK) + d);
            uint4 t = make_uint4(f2tf32(v.x), f2tf32(v.y), f2tf32(v.z), f2tf32(v.w));
            *(uint4*)&ks[buf][jj][d] = t;
        }
#pragma unroll
        for (int it = 0; it < 4; it++) {
            int f = tid + it * 256;
            int jj = f & 63;
            int d = (f >> 6) * 4;
            float4 v = *(const float4*)(Vb + (size_t)(k0 + jj) * (NGROUPS * DK) + d);
            vts[buf][d + 0][jj] = f2tf32(v.x);
            vts[buf][d + 1][jj] = f2tf32(v.y);
            vts[buf][d + 2][jj] = f2tf32(v.z);
            vts[buf][d + 3][jj] = f2tf32(v.w);
        }
    };

    const int row0 = warp * 16 + r;
    const int row1 = row0 + 8;
    const int i0 = q0 + row0;
    const int i1 = q0 + row1;

    float m0 = NEGBIG, l0 = 0.f;
    float m1 = NEGBIG, l1 = 0.f;
    float oc[8][4];
#pragma unroll
    for (int nt = 0; nt < 8; nt++)
#pragma unroll
        for (int i = 0; i < 4; i++) oc[nt][i] = 0.f;

    int jmin = q0 - WINDOW;
    if (jmin < 0) jmin = 0;

    // prologue: stage first tile into buffer 0
    stage_kv(0, jmin);

    int buf = 0;
    for (int k0 = jmin; k0 < q0 + 128; k0 += 64, buf ^= 1) {
        // Single barrier per tile:
        //  - makes tile k0's staging (written pre-loop or last iter) visible
        //  - ensures all warps done reading buf^1 (tile k0-64) before overwrite
        __syncthreads();
        if (k0 + 64 < q0 + 128) stage_kv(buf ^ 1, k0 + 64);

        // ---- S = Q K^T: warp rows x 64 keys (8 n-tiles, 8 k-steps) ----
        float sc[8][4];
#pragma unroll
        for (int nt = 0; nt < 8; nt++)
#pragma unroll
            for (int i = 0; i < 4; i++) sc[nt][i] = 0.f;
#pragma unroll
        for (int kk = 0; kk < 8; kk++) {
            uint32_t a0 = qs[row0][kk * 8 + cl];
            uint32_t a1 = qs[row1][kk * 8 + cl];
            uint32_t a2 = qs[row0][kk * 8 + cl + 4];
            uint32_t a3 = qs[row1][kk * 8 + cl + 4];
#pragma unroll
            for (int nt = 0; nt < 8; nt++) {
                uint32_t b0 = ks[buf][nt * 8 + r][kk * 8 + cl];
                uint32_t b1 = ks[buf][nt * 8 + r][kk * 8 + cl + 4];
                mma_tf32(sc[nt][0], sc[nt][1], sc[nt][2], sc[nt][3],
                         a0, a1, a2, a3, b0, b1);
            }
        }

        // ---- mask + row max (warp-local, quad reduce) ----
        float rmax0 = NEGBIG, rmax1 = NEGBIG;
#pragma unroll
        for (int nt = 0; nt < 8; nt++) {
            int jc = k0 + nt * 8 + 2 * cl;
#pragma unroll
            for (int e = 0; e < 2; e++) {
                int j = jc + e;
                bool ok0 = (j <= i0) && (i0 - j <= WINDOW);
                bool ok1 = (j <= i1) && (i1 - j <= WINDOW);
                sc[nt][e]     = ok0 ? sc[nt][e]     : NEGBIG;
                sc[nt][e + 2] = ok1 ? sc[nt][e + 2] : NEGBIG;
                rmax0 = fmaxf(rmax0, sc[nt][e]);
                rmax1 = fmaxf(rmax1, sc[nt][e + 2]);
            }
        }
        rmax0 = fmaxf(rmax0, __shfl_xor_sync(FULLM, rmax0, 1));
        rmax0 = fmaxf(rmax0, __shfl_xor_sync(FULLM, rmax0, 2));
        rmax1 = fmaxf(rmax1, __shfl_xor_sync(FULLM, rmax1, 1));
        rmax1 = fmaxf(rmax1, __shfl_xor_sync(FULLM, rmax1, 2));

        float m_new0 = fmaxf(m0, rmax0);
        float m_new1 = fmaxf(m1, rmax1);
        float corr0 = __expf(m0 - m_new0);
        float corr1 = __expf(m1 - m_new1);

        // ---- exp + row sums ----
        float sum0 = 0.f, sum1 = 0.f;
#pragma unroll
        for (int nt = 0; nt < 8; nt++) {
            sc[nt][0] = __expf(sc[nt][0] - m_new0);
            sc[nt][1] = __expf(sc[nt][1] - m_new0);
            sc[nt][2] = __expf(sc[nt][2] - m_new1);
            sc[nt][3] = __expf(sc[nt][3] - m_new1);
            sum0 += sc[nt][0] + sc[nt][1];
            sum1 += sc[nt][2] + sc[nt][3];
        }
        sum0 += __shfl_xor_sync(FULLM, sum0, 1);
        sum0 += __shfl_xor_sync(FULLM, sum0, 2);
        sum1 += __shfl_xor_sync(FULLM, sum1, 1);
        sum1 += __shfl_xor_sync(FULLM, sum1, 2);

        l0 = l0 * corr0 + sum0;
        l1 = l1 * corr1 + sum1;
        m0 = m_new0;
        m1 = m_new1;

        // ---- rescale O accumulators ----
#pragma unroll
        for (int nt = 0; nt < 8; nt++) {
            oc[nt][0] *= corr0; oc[nt][1] *= corr0;
            oc[nt][2] *= corr1; oc[nt][3] *= corr1;
        }

        // ---- O += P V: convert C-frag P -> A-frag via quad shuffles ----
        const int qb = lane & ~3;       // quad base lane
        const int s0l = qb + (cl >> 1); // src lane for cols cl
        const int s1l = s0l + 2;        // src lane for cols cl+4
        const bool oddc = (cl & 1);
#pragma unroll
        for (int kk = 0; kk < 8; kk++) {
            float p0 = sc[kk][0], p1 = sc[kk][1];
            float p2 = sc[kk][2], p3 = sc[kk][3];
            float v00 = __shfl_sync(FULLM, p0, s0l);
            float v01 = __shfl_sync(FULLM, p1, s0l);
            float v20 = __shfl_sync(FULLM, p2, s0l);
            float v21 = __shfl_sync(FULLM, p3, s0l);
            float v00b = __shfl_sync(FULLM, p0, s1l);
            float v01b = __shfl_sync(FULLM, p1, s1l);
            float v20b = __shfl_sync(FULLM, p2, s1l);
            float v21b = __shfl_sync(FULLM, p3, s1l);
            uint32_t a0 = f2tf32(oddc ? v01  : v00);   // P[row0][cl]
            uint32_t a1 = f2tf32(oddc ? v21  : v20);   // P[row1][cl]
            uint32_t a2 = f2tf32(oddc ? v01b : v00b);  // P[row0][cl+4]
            uint32_t a3 = f2tf32(oddc ? v21b : v20b);  // P[row1][cl+4]
#pragma unroll
            for (int nt = 0; nt < 8; nt++) {
                uint32_t b0 = vts[buf][nt * 8 + r][kk * 8 + cl];
                uint32_t b1 = vts[buf][nt * 8 + r][kk * 8 + cl + 4];
                mma_tf32(oc[nt][0], oc[nt][1], oc[nt][2], oc[nt][3],
                         a0, a1, a2, a3, b0, b1);
            }
        }
    }

    // ---- epilogue ----
    float inv0 = 1.0f / l0;
    float inv1 = 1.0f / l1;
    float* Ob0 = O + ((size_t)(b * TLEN + i0)) * DMODEL + h * DK;
    float* Ob1 = O + ((size_t)(b * TLEN + i1)) * DMODEL + h * DK;
#pragma unroll
    for (int nt = 0; nt < 8; nt++) {
        int dcol = nt * 8 + 2 * cl;
        *(float2*)(Ob0 + dcol) = make_float2(oc[nt][0] * inv0, oc[nt][1] * inv0);
        *(float2*)(Ob1 + dcol) = make_float2(oc[nt][2] * inv1, oc[nt][3] * inv1);
    }
}

// =======================================================================
// Host launcher
// =======================================================================
extern "C" void kernel_launch(void* const* d_in, const int* in_sizes, int n_in,
                              void* d_out, int out_size)
{
    const float* x  = (const float*)d_in[0];
    const float* WQ = (const float*)d_in[1];
    const float* WK = (const float*)d_in[2];
    const float* WV = (const float*)d_in[3];
    const float* WO = (const float*)d_in[4];
    const int* tpos = (const int*)d_in[5];
    float* out = (float*)d_out;

    float *Qp, *Kp, *Vp, *Ap;
    cudaGetSymbolAddress((void**)&Qp, g_Q);
    cudaGetSymbolAddress((void**)&Kp, g_K);
    cudaGetSymbolAddress((void**)&Vp, g_V);
    cudaGetSymbolAddress((void**)&Ap, g_ATT);

    const int gemm_smem = (2 * BM * SPAD + 2 * BN * SPAD) * 4;          // 73728 B
    const int attn_smem = (128 * 68 + 2 * 64 * 68 + 2 * 64 * 68) * 4;   // 104448 B
    static bool attr_done = false;
    if (!attr_done) {
        cudaFuncSetAttribute(gemm_tf32, cudaFuncAttributeMaxDynamicSharedMemorySize, gemm_smem);
        cudaFuncSetAttribute(attn_mma_kernel, cudaFuncAttributeMaxDynamicSharedMemorySize, attn_smem);
        attr_done = true;
    }

    // 1. Q projection
    gemm_tf32<<<dim3(DMODEL / BN, MTOK / BM, 1), 256, gemm_smem>>>(
        x, WQ, WQ, Qp, Qp, MTOK, DMODEL, DMODEL);
    // 1b. K and V projections fused
    gemm_tf32<<<dim3((NGROUPS * DK) / BN, MTOK / BM, 2), 256, gemm_smem>>>(
        x, WK, WV, Kp, Vp, MTOK, NGROUPS * DK, DMODEL);

    // 2. RoPE (Q and K in one launch)
    {
        int total = NQ_ROPE + NK_ROPE;
        rope_all<<<(total + 255) / 256, 256>>>(Qp, Kp, tpos);
    }

    // 3. Attention (double-buffered K/V, 2 CTAs/SM)
    attn_mma_kernel<<<dim3(TLEN / 128, NHEADS, BATCH), 256, attn_smem>>>(Qp, Kp, Vp, Ap);

    // 4. Output projection
    gemm_tf32<<<dim3(DMODEL / BN, MTOK / BM, 1), 256, gemm_smem>>>(
        Ap, WO, WO, out, out, MTOK, DMODEL, DMODEL);
}

// round 14
// speedup vs baseline: 1.2686x; 1.0101x over previous
#include <cuda_runtime.h>
#include <cuda_bf16.h>
#include <math_constants.h>
#include <cstdint>

// Problem constants
#define BATCH 2
#define TLEN 2048
#define DMODEL 1024
#define NHEADS 16
#define NGROUPS 4
#define DK 64
#define WINDOW 512
#define MTOK (BATCH * TLEN)   // 4096

// -------- scratch (static device globals; no runtime allocation) --------
__device__ float g_Q[MTOK * DMODEL];        // 16 MB
__device__ float g_K[MTOK * NGROUPS * DK];  // 4 MB
__device__ float g_V[MTOK * NGROUPS * DK];  // 4 MB
__device__ float g_ATT[MTOK * DMODEL];      // 16 MB

__device__ __forceinline__ uint32_t f2tf32(float f) {
    uint32_t u;
    asm volatile("cvt.rna.tf32.f32 %0, %1;" : "=r"(u) : "f"(f));
    return u;
}

__device__ __forceinline__ void mma_tf32(
    float& d0, float& d1, float& d2, float& d3,
    uint32_t a0, uint32_t a1, uint32_t a2, uint32_t a3,
    uint32_t b0, uint32_t b1)
{
    asm volatile(
        "mma.sync.aligned.m16n8k8.row.col.f32.tf32.tf32.f32 "
        "{%0,%1,%2,%3}, {%4,%5,%6,%7}, {%8,%9}, {%0,%1,%2,%3};\n"
        : "+f"(d0), "+f"(d1), "+f"(d2), "+f"(d3)
        : "r"(a0), "r"(a1), "r"(a2), "r"(a3), "r"(b0), "r"(b1));
}

__device__ __forceinline__ void cp_async16(uint32_t saddr, const void* gptr) {
    asm volatile("cp.async.cg.shared.global [%0], [%1], 16;"
                 :: "r"(saddr), "l"(gptr));
}
__device__ __forceinline__ void cp_commit() {
    asm volatile("cp.async.commit_group;");
}
__device__ __forceinline__ void cp_wait_all() {
    asm volatile("cp.async.wait_group 0;");
}

#define L2T_OVER_32 0.4152410118609203f   // log2(10000)/32

// =======================================================================
// TF32 GEMM, cp.async double-buffered, WIDE tile, FUSED ROPE epilogue:
// C[M,N] = A[M,K] @ B[N,K]^T ; BM=128 BN=128 BK=32; 8 warps (4m x 2n),
// warp tile 32x64 = 2 m-tiles x 8 n-tiles of m16n8k8.
// blockIdx.z selects (B,C) pair; ropeA/ropeB enable RoPE rotation of the
// output pairs (Q and K projections). Epilogue pairs (c0,c1)/(c2,c3) are
// exactly RoPE (x1,x2) pairs: col = even, col+1 = odd.
// =======================================================================
#define BM 128
#define BN 128
#define BK 32
#define SPAD 36

__global__ __launch_bounds__(256, 2) void gemm_tf32(
    const float* __restrict__ A,
    const float* __restrict__ B0, const float* __restrict__ B1,
    float* __restrict__ C0, float* __restrict__ C1,
    int M, int N, int K,
    const int* __restrict__ pos, int ropeA, int ropeB)
{
    extern __shared__ float gsm[];
    float (*As)[BM][SPAD] = (float(*)[BM][SPAD])gsm;                   // 2 bufs
    float (*Bs)[BN][SPAD] = (float(*)[BN][SPAD])(gsm + 2 * BM * SPAD); // 2 bufs

    const float* B = (blockIdx.z == 0) ? B0 : B1;
    float*       C = (blockIdx.z == 0) ? C0 : C1;
    const int do_rope = (blockIdx.z == 0) ? ropeA : ropeB;

    const int tid  = threadIdx.x;
    const int warp = tid >> 5;
    const int lane = tid & 31;
    const int wm0  = (warp >> 1) * 32;   // 0,32,64,96
    const int wn0  = (warp & 1) * 64;    // 0,64
    const int m0   = blockIdx.y * BM;
    const int n0   = blockIdx.x * BN;

    const int r  = lane >> 2;
    const int cl = lane & 3;

    float c[2][8][4];
#pragma unroll
    for (int mt = 0; mt < 2; mt++)
#pragma unroll
        for (int nt = 0; nt < 8; nt++)
#pragma unroll
            for (int i = 0; i < 4; i++) c[mt][nt][i] = 0.f;

    const int lrow = tid >> 3;        // 0..31
    const int lcol = (tid & 7) * 4;   // 0..28

    auto issue = [&](int buf, int k0) {
#pragma unroll
        for (int p = 0; p < 4; p++)
            cp_async16((uint32_t)__cvta_generic_to_shared(&As[buf][p * 32 + lrow][lcol]),
                       A + (size_t)(m0 + p * 32 + lrow) * K + k0 + lcol);
#pragma unroll
        for (int p = 0; p < 4; p++)
            cp_async16((uint32_t)__cvta_generic_to_shared(&Bs[buf][p * 32 + lrow][lcol]),
                       B + (size_t)(n0 + p * 32 + lrow) * K + k0 + lcol);
        cp_commit();
    };

    issue(0, 0);
    int cur = 0;

    for (int k0 = 0; k0 < K; k0 += BK) {
        cp_wait_all();
        __syncthreads();
        if (k0 + BK < K) issue(cur ^ 1, k0 + BK);

#pragma unroll
        for (int kk = 0; kk < BK; kk += 8) {
            uint32_t af[2][4], bf[8][2];
#pragma unroll
            for (int mt = 0; mt < 2; mt++) {
                af[mt][0] = f2tf32(As[cur][wm0 + mt * 16 + r][kk + cl]);
                af[mt][1] = f2tf32(As[cur][wm0 + mt * 16 + r + 8][kk + cl]);
                af[mt][2] = f2tf32(As[cur][wm0 + mt * 16 + r][kk + cl + 4]);
                af[mt][3] = f2tf32(As[cur][wm0 + mt * 16 + r + 8][kk + cl + 4]);
            }
#pragma unroll
            for (int nt = 0; nt < 8; nt++) {
                bf[nt][0] = f2tf32(Bs[cur][wn0 + nt * 8 + r][kk + cl]);
                bf[nt][1] = f2tf32(Bs[cur][wn0 + nt * 8 + r][kk + cl + 4]);
            }
#pragma unroll
            for (int mt = 0; mt < 2; mt++)
#pragma unroll
                for (int nt = 0; nt < 8; nt++)
                    mma_tf32(c[mt][nt][0], c[mt][nt][1], c[mt][nt][2], c[mt][nt][3],
                             af[mt][0], af[mt][1], af[mt][2], af[mt][3],
                             bf[nt][0], bf[nt][1]);
        }
        cur ^= 1;
    }

    // ---- epilogue (optionally fused RoPE) ----
#pragma unroll
    for (int mt = 0; mt < 2; mt++) {
        int rowa = m0 + wm0 + mt * 16 + r;
        int rowb = rowa + 8;
        float posa = 0.f, posb = 0.f;
        if (do_rope) {
            posa = (float)pos[rowa & (TLEN - 1)];
            posb = (float)pos[rowb & (TLEN - 1)];
        }
#pragma unroll
        for (int nt = 0; nt < 8; nt++) {
            int col = n0 + wn0 + nt * 8 + 2 * cl;
            float v0 = c[mt][nt][0], v1 = c[mt][nt][1];  // row rowa: (x1,x2)
            float v2 = c[mt][nt][2], v3 = c[mt][nt][3];  // row rowb: (x1,x2)
            if (do_rope) {
                int p = (col & 63) >> 1;
                float inv = exp2f(-(float)p * L2T_OVER_32);
                float sa, ca, sb, cb;
                sincosf(posa * inv, &sa, &ca);
                sincosf(posb * inv, &sb, &cb);
                float r0 = v0 * ca - v1 * sa;
                float r1 = v0 * sa + v1 * ca;
                float r2 = v2 * cb - v3 * sb;
                float r3 = v2 * sb + v3 * cb;
                v0 = r0; v1 = r1; v2 = r2; v3 = r3;
            }
            *(float2*)(C + (size_t)rowa * N + col) = make_float2(v0, v1);
            *(float2*)(C + (size_t)rowb * N + col) = make_float2(v2, v3);
        }
    }
}

// =======================================================================
// Tensor-core flash attention (R11 version, measured 109.1us):
// 128q x 64k tiles; warp owns 16 rows; softmax warp-local; P via
// quad-shuffle C->A conversion. Row-major smem tiles (conflict-free STS).
// =======================================================================
#define NEGBIG (-1e30f)
#define FULLM 0xffffffffu

__global__ __launch_bounds__(256) void attn_mma_kernel(
    const float* __restrict__ Q, const float* __restrict__ K,
    const float* __restrict__ V, float* __restrict__ O)
{
    extern __shared__ uint32_t asm_[];
    uint32_t (*qs)[68]  = (uint32_t(*)[68])asm_;
    uint32_t (*ks)[68]  = (uint32_t(*)[68])(asm_ + 128 * 68);
    uint32_t (*vts)[68] = (uint32_t(*)[68])(asm_ + 128 * 68 + 64 * 68);

    const int tid  = threadIdx.x;
    const int warp = tid >> 5;
    const int lane = tid & 31;
    const int r    = lane >> 2;   // 0..7
    const int cl   = lane & 3;    // 0..3

    const int q0 = blockIdx.x * 128;
    const int h  = blockIdx.y;
    const int b  = blockIdx.z;
    const int g  = h >> 2;

    const float* Qb = Q + ((size_t)(b * TLEN + q0)) * DMODEL + h * DK;
    const float* Kb = K + ((size_t)b * TLEN) * (NGROUPS * DK) + g * DK;
    const float* Vb = V + ((size_t)b * TLEN) * (NGROUPS * DK) + g * DK;

    // ---- stage Q (128x64, scaled by 1/8, tf32) ----
#pragma unroll
    for (int it = 0; it < 8; it++) {
        int f = tid + it * 256;
        int row = f >> 4;
        int d = (f & 15) * 4;
        float4 v = *(const float4*)(Qb + (size_t)row * DMODEL + d);
        uint4 t = make_uint4(f2tf32(v.x * 0.125f), f2tf32(v.y * 0.125f),
                             f2tf32(v.z * 0.125f), f2tf32(v.w * 0.125f));
        *(uint4*)&qs[row][d] = t;
    }

    const int row0 = warp * 16 + r;
    const int row1 = row0 + 8;
    const int i0 = q0 + row0;
    const int i1 = q0 + row1;

    float m0 = NEGBIG, l0 = 0.f;
    float m1 = NEGBIG, l1 = 0.f;
    float oc[8][4];
#pragma unroll
    for (int nt = 0; nt < 8; nt++)
#pragma unroll
        for (int i = 0; i < 4; i++) oc[nt][i] = 0.f;

    int jmin = q0 - WINDOW;
    if (jmin < 0) jmin = 0;

    for (int k0 = jmin; k0 < q0 + 128; k0 += 64) {
        __syncthreads();  // prior iteration's reads of ks/vts finished

        // ---- stage K tile [64 keys][64 d] ----
#pragma unroll
        for (int it = 0; it < 4; it++) {
            int f = tid + it * 256;
            int jj = f >> 4;
            int d = (f & 15) * 4;
            float4 v = *(const float4*)(Kb + (size_t)(k0 + jj) * (NGROUPS * DK) + d);
            uint4 t = make_uint4(f2tf32(v.x), f2tf32(v.y), f2tf32(v.z), f2tf32(v.w));
            *(uint4*)&ks[jj][d] = t;
        }
        // ---- stage V^T tile [64 d][64 keys] ----
#pragma unroll
        for (int it = 0; it < 4; it++) {
            int f = tid + it * 256;
            int jj = f & 63;
            int d = (f >> 6) * 4;
            float4 v = *(const float4*)(Vb + (size_t)(k0 + jj) * (NGROUPS * DK) + d);
            vts[d + 0][jj] = f2tf32(v.x);
            vts[d + 1][jj] = f2tf32(v.y);
            vts[d + 2][jj] = f2tf32(v.z);
            vts[d + 3][jj] = f2tf32(v.w);
        }
        __syncthreads();

        // ---- S = Q K^T: warp rows x 64 keys (8 n-tiles, 8 k-steps) ----
        float sc[8][4];
#pragma unroll
        for (int nt = 0; nt < 8; nt++)
#pragma unroll
            for (int i = 0; i < 4; i++) sc[nt][i] = 0.f;
#pragma unroll
        for (int kk = 0; kk < 8; kk++) {
            uint32_t a0 = qs[row0][kk * 8 + cl];
            uint32_t a1 = qs[row1][kk * 8 + cl];
            uint32_t a2 = qs[row0][kk * 8 + cl + 4];
            uint32_t a3 = qs[row1][kk * 8 + cl + 4];
#pragma unroll
            for (int nt = 0; nt < 8; nt++) {
                uint32_t b0 = ks[nt * 8 + r][kk * 8 + cl];
                uint32_t b1 = ks[nt * 8 + r][kk * 8 + cl + 4];
                mma_tf32(sc[nt][0], sc[nt][1], sc[nt][2], sc[nt][3],
                         a0, a1, a2, a3, b0, b1);
            }
        }

        // ---- mask + row max (warp-local, quad reduce) ----
        float rmax0 = NEGBIG, rmax1 = NEGBIG;
#pragma unroll
        for (int nt = 0; nt < 8; nt++) {
            int jc = k0 + nt * 8 + 2 * cl;
#pragma unroll
            for (int e = 0; e < 2; e++) {
                int j = jc + e;
                bool ok0 = (j <= i0) && (i0 - j <= WINDOW);
                bool ok1 = (j <= i1) && (i1 - j <= WINDOW);
                sc[nt][e]     = ok0 ? sc[nt][e]     : NEGBIG;
                sc[nt][e + 2] = ok1 ? sc[nt][e + 2] : NEGBIG;
                rmax0 = fmaxf(rmax0, sc[nt][e]);
                rmax1 = fmaxf(rmax1, sc[nt][e + 2]);
            }
        }
        rmax0 = fmaxf(rmax0, __shfl_xor_sync(FULLM, rmax0, 1));
        rmax0 = fmaxf(rmax0, __shfl_xor_sync(FULLM, rmax0, 2));
        rmax1 = fmaxf(rmax1, __shfl_xor_sync(FULLM, rmax1, 1));
        rmax1 = fmaxf(rmax1, __shfl_xor_sync(FULLM, rmax1, 2));

        float m_new0 = fmaxf(m0, rmax0);
        float m_new1 = fmaxf(m1, rmax1);
        float corr0 = __expf(m0 - m_new0);
        float corr1 = __expf(m1 - m_new1);

        // ---- exp + row sums ----
        float sum0 = 0.f, sum1 = 0.f;
#pragma unroll
        for (int nt = 0; nt < 8; nt++) {
            sc[nt][0] = __expf(sc[nt][0] - m_new0);
            sc[nt][1] = __expf(sc[nt][1] - m_new0);
            sc[nt][2] = __expf(sc[nt][2] - m_new1);
            sc[nt][3] = __expf(sc[nt][3] - m_new1);
            sum0 += sc[nt][0] + sc[nt][1];
            sum1 += sc[nt][2] + sc[nt][3];
        }
        sum0 += __shfl_xor_sync(FULLM, sum0, 1);
        sum0 += __shfl_xor_sync(FULLM, sum0, 2);
        sum1 += __shfl_xor_sync(FULLM, sum1, 1);
        sum1 += __shfl_xor_sync(FULLM, sum1, 2);

        l0 = l0 * corr0 + sum0;
        l1 = l1 * corr1 + sum1;
        m0 = m_new0;
        m1 = m_new1;

        // ---- rescale O accumulators ----
#pragma unroll
        for (int nt = 0; nt < 8; nt++) {
            oc[nt][0] *= corr0; oc[nt][1] *= corr0;
            oc[nt][2] *= corr1; oc[nt][3] *= corr1;
        }

        // ---- O += P V: convert C-frag P -> A-frag via quad shuffles ----
        const int qb = lane & ~3;       // quad base lane
        const int s0l = qb + (cl >> 1); // src lane for cols cl
        const int s1l = s0l + 2;        // src lane for cols cl+4
        const bool oddc = (cl & 1);
#pragma unroll
        for (int kk = 0; kk < 8; kk++) {
            float p0 = sc[kk][0], p1 = sc[kk][1];
            float p2 = sc[kk][2], p3 = sc[kk][3];
            float v00 = __shfl_sync(FULLM, p0, s0l);
            float v01 = __shfl_sync(FULLM, p1, s0l);
            float v20 = __shfl_sync(FULLM, p2, s0l);
            float v21 = __shfl_sync(FULLM, p3, s0l);
            float v00b = __shfl_sync(FULLM, p0, s1l);
            float v01b = __shfl_sync(FULLM, p1, s1l);
            float v20b = __shfl_sync(FULLM, p2, s1l);
            float v21b = __shfl_sync(FULLM, p3, s1l);
            uint32_t a0 = f2tf32(oddc ? v01  : v00);   // P[row0][cl]
            uint32_t a1 = f2tf32(oddc ? v21  : v20);   // P[row1][cl]
            uint32_t a2 = f2tf32(oddc ? v01b : v00b);  // P[row0][cl+4]
            uint32_t a3 = f2tf32(oddc ? v21b : v20b);  // P[row1][cl+4]
#pragma unroll
            for (int nt = 0; nt < 8; nt++) {
                uint32_t b0 = vts[nt * 8 + r][kk * 8 + cl];
                uint32_t b1 = vts[nt * 8 + r][kk * 8 + cl + 4];
                mma_tf32(oc[nt][0], oc[nt][1], oc[nt][2], oc[nt][3],
                         a0, a1, a2, a3, b0, b1);
            }
        }
    }

    // ---- epilogue ----
    float inv0 = 1.0f / l0;
    float inv1 = 1.0f / l1;
    float* Ob0 = O + ((size_t)(b * TLEN + i0)) * DMODEL + h * DK;
    float* Ob1 = O + ((size_t)(b * TLEN + i1)) * DMODEL + h * DK;
#pragma unroll
    for (int nt = 0; nt < 8; nt++) {
        int dcol = nt * 8 + 2 * cl;
        *(float2*)(Ob0 + dcol) = make_float2(oc[nt][0] * inv0, oc[nt][1] * inv0);
        *(float2*)(Ob1 + dcol) = make_float2(oc[nt][2] * inv1, oc[nt][3] * inv1);
    }
}

// =======================================================================
// Host launcher
// =======================================================================
extern "C" void kernel_launch(void* const* d_in, const int* in_sizes, int n_in,
                              void* d_out, int out_size)
{
    const float* x  = (const float*)d_in[0];
    const float* WQ = (const float*)d_in[1];
    const float* WK = (const float*)d_in[2];
    const float* WV = (const float*)d_in[3];
    const float* WO = (const float*)d_in[4];
    const int* tpos = (const int*)d_in[5];
    float* out = (float*)d_out;

    float *Qp, *Kp, *Vp, *Ap;
    cudaGetSymbolAddress((void**)&Qp, g_Q);
    cudaGetSymbolAddress((void**)&Kp, g_K);
    cudaGetSymbolAddress((void**)&Vp, g_V);
    cudaGetSymbolAddress((void**)&Ap, g_ATT);

    const int gemm_smem = (2 * BM * SPAD + 2 * BN * SPAD) * 4;   // 73728 B
    const int attn_smem = (128 * 68 + 64 * 68 + 64 * 68) * 4;    // 69632 B
    static bool attr_done = false;
    if (!attr_done) {
        cudaFuncSetAttribute(gemm_tf32, cudaFuncAttributeMaxDynamicSharedMemorySize, gemm_smem);
        cudaFuncSetAttribute(attn_mma_kernel, cudaFuncAttributeMaxDynamicSharedMemorySize, attn_smem);
        attr_done = true;
    }

    // 1. Q projection with fused RoPE
    gemm_tf32<<<dim3(DMODEL / BN, MTOK / BM, 1), 256, gemm_smem>>>(
        x, WQ, WQ, Qp, Qp, MTOK, DMODEL, DMODEL, tpos, 1, 1);
    // 1b. K (fused RoPE) and V projections in one launch
    gemm_tf32<<<dim3((NGROUPS * DK) / BN, MTOK / BM, 2), 256, gemm_smem>>>(
        x, WK, WV, Kp, Vp, MTOK, NGROUPS * DK, DMODEL, tpos, 1, 0);

    // 2. Attention (R11 kernel: 128q x 64k tiles, single-buffered)
    attn_mma_kernel<<<dim3(TLEN / 128, NHEADS, BATCH), 256, attn_smem>>>(Qp, Kp, Vp, Ap);

    // 3. Output projection (no rope)
    gemm_tf32<<<dim3(DMODEL / BN, MTOK / BM, 1), 256, gemm_smem>>>(
        Ap, WO, WO, out, out, MTOK, DMODEL, DMODEL, tpos, 0, 0);
}

// round 16
// speedup vs baseline: 1.3370x; 1.0539x over previous
#include <cuda_runtime.h>
#include <cuda_bf16.h>
#include <math_constants.h>
#include <cstdint>

// Problem constants
#define BATCH 2
#define TLEN 2048
#define DMODEL 1024
#define NHEADS 16
#define NGROUPS 4
#define DK 64
#define WINDOW 512
#define MTOK (BATCH * TLEN)   // 4096

// -------- scratch (static device globals; no runtime allocation) --------
__device__ float g_Q[MTOK * DMODEL];        // 16 MB
__device__ float g_K[MTOK * NGROUPS * DK];  // 4 MB
__device__ float g_V[MTOK * NGROUPS * DK];  // 4 MB
__device__ float g_ATT[MTOK * DMODEL];      // 16 MB (tf32-rounded by attn epilogue)
// tf32-pre-rounded weights
__device__ float g_WQ[DMODEL * DMODEL];     // 4 MB
__device__ float g_WK[NGROUPS * DK * DMODEL];
__device__ float g_WV[NGROUPS * DK * DMODEL];
__device__ float g_WO[DMODEL * DMODEL];

__device__ __forceinline__ uint32_t f2tf32(float f) {
    uint32_t u;
    asm volatile("cvt.rna.tf32.f32 %0, %1;" : "=r"(u) : "f"(f));
    return u;
}

__device__ __forceinline__ void mma_tf32(
    float& d0, float& d1, float& d2, float& d3,
    uint32_t a0, uint32_t a1, uint32_t a2, uint32_t a3,
    uint32_t b0, uint32_t b1)
{
    asm volatile(
        "mma.sync.aligned.m16n8k8.row.col.f32.tf32.tf32.f32 "
        "{%0,%1,%2,%3}, {%4,%5,%6,%7}, {%8,%9}, {%0,%1,%2,%3};\n"
        : "+f"(d0), "+f"(d1), "+f"(d2), "+f"(d3)
        : "r"(a0), "r"(a1), "r"(a2), "r"(a3), "r"(b0), "r"(b1));
}

__device__ __forceinline__ void cp_async16(uint32_t saddr, const void* gptr) {
    asm volatile("cp.async.cg.shared.global [%0], [%1], 16;"
                 :: "r"(saddr), "l"(gptr));
}
__device__ __forceinline__ void cp_commit() {
    asm volatile("cp.async.commit_group;");
}
__device__ __forceinline__ void cp_wait_all() {
    asm volatile("cp.async.wait_group 0;");
}

#define L2T_OVER_32 0.4152410118609203f   // log2(10000)/32

// =======================================================================
// Weight pre-round: cvt.rna all four weight matrices to tf32 (in fp32
// container). Values become exactly representable -> GEMM can feed raw
// bits to mma with identical numerics and zero mainloop cvts on B.
// =======================================================================
#define WQ_ELEMS (DMODEL * DMODEL)
#define WKV_ELEMS (NGROUPS * DK * DMODEL)
#define WTOTAL (2 * WQ_ELEMS + 2 * WKV_ELEMS)

__global__ void preround_weights(
    const float* __restrict__ WQ, const float* __restrict__ WK,
    const float* __restrict__ WV, const float* __restrict__ WO,
    float* __restrict__ oWQ, float* __restrict__ oWK,
    float* __restrict__ oWV, float* __restrict__ oWO)
{
    int idx4 = blockIdx.x * blockDim.x + threadIdx.x;
    int idx = idx4 * 4;
    if (idx >= WTOTAL) return;
    const float* src;
    float* dst;
    int local;
    if (idx < WQ_ELEMS) { src = WQ; dst = oWQ; local = idx; }
    else if (idx < WQ_ELEMS + WKV_ELEMS) { src = WK; dst = oWK; local = idx - WQ_ELEMS; }
    else if (idx < WQ_ELEMS + 2 * WKV_ELEMS) { src = WV; dst = oWV; local = idx - WQ_ELEMS - WKV_ELEMS; }
    else { src = WO; dst = oWO; local = idx - WQ_ELEMS - 2 * WKV_ELEMS; }
    float4 v = *(const float4*)(src + local);
    uint4 t = make_uint4(f2tf32(v.x), f2tf32(v.y), f2tf32(v.z), f2tf32(v.w));
    *(float4*)(dst + local) = *(float4*)&t;
}

// =======================================================================
// TF32 GEMM, cp.async double-buffered, WIDE tile, FUSED ROPE epilogue.
// B is ALWAYS pre-rounded tf32 (no cvt). CVA: cvt A-fragments (1 when A
// is raw fp32 x; 0 when A is pre-rounded, e.g. ATT from attention).
// =======================================================================
#define BM 128
#define BN 128
#define BK 32
#define SPAD 36

template <int CVA>
__global__ __launch_bounds__(256, 2) void gemm_tf32(
    const float* __restrict__ A,
    const float* __restrict__ B0, const float* __restrict__ B1,
    float* __restrict__ C0, float* __restrict__ C1,
    int M, int N, int K,
    const int* __restrict__ pos, int ropeA, int ropeB)
{
    extern __shared__ float gsm[];
    float (*As)[BM][SPAD] = (float(*)[BM][SPAD])gsm;
    float (*Bs)[BN][SPAD] = (float(*)[BN][SPAD])(gsm + 2 * BM * SPAD);

    const float* B = (blockIdx.z == 0) ? B0 : B1;
    float*       C = (blockIdx.z == 0) ? C0 : C1;
    const int do_rope = (blockIdx.z == 0) ? ropeA : ropeB;

    const int tid  = threadIdx.x;
    const int warp = tid >> 5;
    const int lane = tid & 31;
    const int wm0  = (warp >> 1) * 32;
    const int wn0  = (warp & 1) * 64;
    const int m0   = blockIdx.y * BM;
    const int n0   = blockIdx.x * BN;

    const int r  = lane >> 2;
    const int cl = lane & 3;

    float c[2][8][4];
#pragma unroll
    for (int mt = 0; mt < 2; mt++)
#pragma unroll
        for (int nt = 0; nt < 8; nt++)
#pragma unroll
            for (int i = 0; i < 4; i++) c[mt][nt][i] = 0.f;

    const int lrow = tid >> 3;
    const int lcol = (tid & 7) * 4;

    auto issue = [&](int buf, int k0) {
#pragma unroll
        for (int p = 0; p < 4; p++)
            cp_async16((uint32_t)__cvta_generic_to_shared(&As[buf][p * 32 + lrow][lcol]),
                       A + (size_t)(m0 + p * 32 + lrow) * K + k0 + lcol);
#pragma unroll
        for (int p = 0; p < 4; p++)
            cp_async16((uint32_t)__cvta_generic_to_shared(&Bs[buf][p * 32 + lrow][lcol]),
                       B + (size_t)(n0 + p * 32 + lrow) * K + k0 + lcol);
        cp_commit();
    };

    issue(0, 0);
    int cur = 0;

    for (int k0 = 0; k0 < K; k0 += BK) {
        cp_wait_all();
        __syncthreads();
        if (k0 + BK < K) issue(cur ^ 1, k0 + BK);

#pragma unroll
        for (int kk = 0; kk < BK; kk += 8) {
            uint32_t af[2][4], bf[8][2];
#pragma unroll
            for (int mt = 0; mt < 2; mt++) {
                if (CVA) {
                    af[mt][0] = f2tf32(As[cur][wm0 + mt * 16 + r][kk + cl]);
                    af[mt][1] = f2tf32(As[cur][wm0 + mt * 16 + r + 8][kk + cl]);
                    af[mt][2] = f2tf32(As[cur][wm0 + mt * 16 + r][kk + cl + 4]);
                    af[mt][3] = f2tf32(As[cur][wm0 + mt * 16 + r + 8][kk + cl + 4]);
                } else {
                    af[mt][0] = __float_as_uint(As[cur][wm0 + mt * 16 + r][kk + cl]);
                    af[mt][1] = __float_as_uint(As[cur][wm0 + mt * 16 + r + 8][kk + cl]);
                    af[mt][2] = __float_as_uint(As[cur][wm0 + mt * 16 + r][kk + cl + 4]);
                    af[mt][3] = __float_as_uint(As[cur][wm0 + mt * 16 + r + 8][kk + cl + 4]);
                }
            }
#pragma unroll
            for (int nt = 0; nt < 8; nt++) {
                bf[nt][0] = __float_as_uint(Bs[cur][wn0 + nt * 8 + r][kk + cl]);
                bf[nt][1] = __float_as_uint(Bs[cur][wn0 + nt * 8 + r][kk + cl + 4]);
            }
#pragma unroll
            for (int mt = 0; mt < 2; mt++)
#pragma unroll
                for (int nt = 0; nt < 8; nt++)
                    mma_tf32(c[mt][nt][0], c[mt][nt][1], c[mt][nt][2], c[mt][nt][3],
                             af[mt][0], af[mt][1], af[mt][2], af[mt][3],
                             bf[nt][0], bf[nt][1]);
        }
        cur ^= 1;
    }

    // ---- epilogue (optionally fused RoPE) ----
#pragma unroll
    for (int mt = 0; mt < 2; mt++) {
        int rowa = m0 + wm0 + mt * 16 + r;
        int rowb = rowa + 8;
        float posa = 0.f, posb = 0.f;
        if (do_rope) {
            posa = (float)pos[rowa & (TLEN - 1)];
            posb = (float)pos[rowb & (TLEN - 1)];
        }
#pragma unroll
        for (int nt = 0; nt < 8; nt++) {
            int col = n0 + wn0 + nt * 8 + 2 * cl;
            float v0 = c[mt][nt][0], v1 = c[mt][nt][1];
            float v2 = c[mt][nt][2], v3 = c[mt][nt][3];
            if (do_rope) {
                int p = (col & 63) >> 1;
                float inv = exp2f(-(float)p * L2T_OVER_32);
                float sa, ca, sb, cb;
                sincosf(posa * inv, &sa, &ca);
                sincosf(posb * inv, &sb, &cb);
                float r0 = v0 * ca - v1 * sa;
                float r1 = v0 * sa + v1 * ca;
                float r2 = v2 * cb - v3 * sb;
                float r3 = v2 * sb + v3 * cb;
                v0 = r0; v1 = r1; v2 = r2; v3 = r3;
            }
            *(float2*)(C + (size_t)rowa * N + col) = make_float2(v0, v1);
            *(float2*)(C + (size_t)rowb * N + col) = make_float2(v2, v3);
        }
    }
}

// =======================================================================
// Tensor-core flash attention (R11 kernel, measured 109.1us), with the
// epilogue additionally tf32-rounding the ATT output (so the WO GEMM can
// skip A cvts; cvt(x*inv) here == cvt at WO load time -> identical bits).
// =======================================================================
#define NEGBIG (-1e30f)
#define FULLM 0xffffffffu

__global__ __launch_bounds__(256) void attn_mma_kernel(
    const float* __restrict__ Q, const float* __restrict__ K,
    const float* __restrict__ V, float* __restrict__ O)
{
    extern __shared__ uint32_t asm_[];
    uint32_t (*qs)[68]  = (uint32_t(*)[68])asm_;
    uint32_t (*ks)[68]  = (uint32_t(*)[68])(asm_ + 128 * 68);
    uint32_t (*vts)[68] = (uint32_t(*)[68])(asm_ + 128 * 68 + 64 * 68);

    const int tid  = threadIdx.x;
    const int warp = tid >> 5;
    const int lane = tid & 31;
    const int r    = lane >> 2;
    const int cl   = lane & 3;

    const int q0 = blockIdx.x * 128;
    const int h  = blockIdx.y;
    const int b  = blockIdx.z;
    const int g  = h >> 2;

    const float* Qb = Q + ((size_t)(b * TLEN + q0)) * DMODEL + h * DK;
    const float* Kb = K + ((size_t)b * TLEN) * (NGROUPS * DK) + g * DK;
    const float* Vb = V + ((size_t)b * TLEN) * (NGROUPS * DK) + g * DK;

    // ---- stage Q (128x64, scaled by 1/8, tf32) ----
#pragma unroll
    for (int it = 0; it < 8; it++) {
        int f = tid + it * 256;
        int row = f >> 4;
        int d = (f & 15) * 4;
        float4 v = *(const float4*)(Qb + (size_t)row * DMODEL + d);
        uint4 t = make_uint4(f2tf32(v.x * 0.125f), f2tf32(v.y * 0.125f),
                             f2tf32(v.z * 0.125f), f2tf32(v.w * 0.125f));
        *(uint4*)&qs[row][d] = t;
    }

    const int row0 = warp * 16 + r;
    const int row1 = row0 + 8;
    const int i0 = q0 + row0;
    const int i1 = q0 + row1;

    float m0 = NEGBIG, l0 = 0.f;
    float m1 = NEGBIG, l1 = 0.f;
    float oc[8][4];
#pragma unroll
    for (int nt = 0; nt < 8; nt++)
#pragma unroll
        for (int i = 0; i < 4; i++) oc[nt][i] = 0.f;

    int jmin = q0 - WINDOW;
    if (jmin < 0) jmin = 0;

    for (int k0 = jmin; k0 < q0 + 128; k0 += 64) {
        __syncthreads();

        // ---- stage K tile [64 keys][64 d] ----
#pragma unroll
        for (int it = 0; it < 4; it++) {
            int f = tid + it * 256;
            int jj = f >> 4;
            int d = (f & 15) * 4;
            float4 v = *(const float4*)(Kb + (size_t)(k0 + jj) * (NGROUPS * DK) + d);
            uint4 t = make_uint4(f2tf32(v.x), f2tf32(v.y), f2tf32(v.z), f2tf32(v.w));
            *(uint4*)&ks[jj][d] = t;
        }
        // ---- stage V^T tile [64 d][64 keys] ----
#pragma unroll
        for (int it = 0; it < 4; it++) {
            int f = tid + it * 256;
            int jj = f & 63;
            int d = (f >> 6) * 4;
            float4 v = *(const float4*)(Vb + (size_t)(k0 + jj) * (NGROUPS * DK) + d);
            vts[d + 0][jj] = f2tf32(v.x);
            vts[d + 1][jj] = f2tf32(v.y);
            vts[d + 2][jj] = f2tf32(v.z);
            vts[d + 3][jj] = f2tf32(v.w);
        }
        __syncthreads();

        // ---- S = Q K^T ----
        float sc[8][4];
#pragma unroll
        for (int nt = 0; nt < 8; nt++)
#pragma unroll
            for (int i = 0; i < 4; i++) sc[nt][i] = 0.f;
#pragma unroll
        for (int kk = 0; kk < 8; kk++) {
            uint32_t a0 = qs[row0][kk * 8 + cl];
            uint32_t a1 = qs[row1][kk * 8 + cl];
            uint32_t a2 = qs[row0][kk * 8 + cl + 4];
            uint32_t a3 = qs[row1][kk * 8 + cl + 4];
#pragma unroll
            for (int nt = 0; nt < 8; nt++) {
                uint32_t b0 = ks[nt * 8 + r][kk * 8 + cl];
                uint32_t b1 = ks[nt * 8 + r][kk * 8 + cl + 4];
                mma_tf32(sc[nt][0], sc[nt][1], sc[nt][2], sc[nt][3],
                         a0, a1, a2, a3, b0, b1);
            }
        }

        // ---- mask + row max ----
        float rmax0 = NEGBIG, rmax1 = NEGBIG;
#pragma unroll
        for (int nt = 0; nt < 8; nt++) {
            int jc = k0 + nt * 8 + 2 * cl;
#pragma unroll
            for (int e = 0; e < 2; e++) {
                int j = jc + e;
                bool ok0 = (j <= i0) && (i0 - j <= WINDOW);
                bool ok1 = (j <= i1) && (i1 - j <= WINDOW);
                sc[nt][e]     = ok0 ? sc[nt][e]     : NEGBIG;
                sc[nt][e + 2] = ok1 ? sc[nt][e + 2] : NEGBIG;
                rmax0 = fmaxf(rmax0, sc[nt][e]);
                rmax1 = fmaxf(rmax1, sc[nt][e + 2]);
            }
        }
        rmax0 = fmaxf(rmax0, __shfl_xor_sync(FULLM, rmax0, 1));
        rmax0 = fmaxf(rmax0, __shfl_xor_sync(FULLM, rmax0, 2));
        rmax1 = fmaxf(rmax1, __shfl_xor_sync(FULLM, rmax1, 1));
        rmax1 = fmaxf(rmax1, __shfl_xor_sync(FULLM, rmax1, 2));

        float m_new0 = fmaxf(m0, rmax0);
        float m_new1 = fmaxf(m1, rmax1);
        float corr0 = __expf(m0 - m_new0);
        float corr1 = __expf(m1 - m_new1);

        // ---- exp + row sums ----
        float sum0 = 0.f, sum1 = 0.f;
#pragma unroll
        for (int nt = 0; nt < 8; nt++) {
            sc[nt][0] = __expf(sc[nt][0] - m_new0);
            sc[nt][1] = __expf(sc[nt][1] - m_new0);
            sc[nt][2] = __expf(sc[nt][2] - m_new1);
            sc[nt][3] = __expf(sc[nt][3] - m_new1);
            sum0 += sc[nt][0] + sc[nt][1];
            sum1 += sc[nt][2] + sc[nt][3];
        }
        sum0 += __shfl_xor_sync(FULLM, sum0, 1);
        sum0 += __shfl_xor_sync(FULLM, sum0, 2);
        sum1 += __shfl_xor_sync(FULLM, sum1, 1);
        sum1 += __shfl_xor_sync(FULLM, sum1, 2);

        l0 = l0 * corr0 + sum0;
        l1 = l1 * corr1 + sum1;
        m0 = m_new0;
        m1 = m_new1;

#pragma unroll
        for (int nt = 0; nt < 8; nt++) {
            oc[nt][0] *= corr0; oc[nt][1] *= corr0;
            oc[nt][2] *= corr1; oc[nt][3] *= corr1;
        }

        // ---- O += P V ----
        const int qb = lane & ~3;
        const int s0l = qb + (cl >> 1);
        const int s1l = s0l + 2;
        const bool oddc = (cl & 1);
#pragma unroll
        for (int kk = 0; kk < 8; kk++) {
            float p0 = sc[kk][0], p1 = sc[kk][1];
            float p2 = sc[kk][2], p3 = sc[kk][3];
            float v00 = __shfl_sync(FULLM, p0, s0l);
            float v01 = __shfl_sync(FULLM, p1, s0l);
            float v20 = __shfl_sync(FULLM, p2, s0l);
            float v21 = __shfl_sync(FULLM, p3, s0l);
            float v00b = __shfl_sync(FULLM, p0, s1l);
            float v01b = __shfl_sync(FULLM, p1, s1l);
            float v20b = __shfl_sync(FULLM, p2, s1l);
            float v21b = __shfl_sync(FULLM, p3, s1l);
            uint32_t a0 = f2tf32(oddc ? v01  : v00);
            uint32_t a1 = f2tf32(oddc ? v21  : v20);
            uint32_t a2 = f2tf32(oddc ? v01b : v00b);
            uint32_t a3 = f2tf32(oddc ? v21b : v20b);
#pragma unroll
            for (int nt = 0; nt < 8; nt++) {
                uint32_t b0 = vts[nt * 8 + r][kk * 8 + cl];
                uint32_t b1 = vts[nt * 8 + r][kk * 8 + cl + 4];
                mma_tf32(oc[nt][0], oc[nt][1], oc[nt][2], oc[nt][3],
                         a0, a1, a2, a3, b0, b1);
            }
        }
    }

    // ---- epilogue: normalize + tf32-round (feeds WO GEMM pre-rounded) ----
    float inv0 = 1.0f / l0;
    float inv1 = 1.0f / l1;
    float* Ob0 = O + ((size_t)(b * TLEN + i0)) * DMODEL + h * DK;
    float* Ob1 = O + ((size_t)(b * TLEN + i1)) * DMODEL + h * DK;
#pragma unroll
    for (int nt = 0; nt < 8; nt++) {
        int dcol = nt * 8 + 2 * cl;
        uint2 w0 = make_uint2(f2tf32(oc[nt][0] * inv0), f2tf32(oc[nt][1] * inv0));
        uint2 w1 = make_uint2(f2tf32(oc[nt][2] * inv1), f2tf32(oc[nt][3] * inv1));
        *(uint2*)(Ob0 + dcol) = w0;
        *(uint2*)(Ob1 + dcol) = w1;
    }
}

// =======================================================================
// Host launcher
// =======================================================================
extern "C" void kernel_launch(void* const* d_in, const int* in_sizes, int n_in,
                              void* d_out, int out_size)
{
    const float* x  = (const float*)d_in[0];
    const float* WQ = (const float*)d_in[1];
    const float* WK = (const float*)d_in[2];
    const float* WV = (const float*)d_in[3];
    const float* WO = (const float*)d_in[4];
    const int* tpos = (const int*)d_in[5];
    float* out = (float*)d_out;

    float *Qp, *Kp, *Vp, *Ap, *WQp, *WKp, *WVp, *WOp;
    cudaGetSymbolAddress((void**)&Qp, g_Q);
    cudaGetSymbolAddress((void**)&Kp, g_K);
    cudaGetSymbolAddress((void**)&Vp, g_V);
    cudaGetSymbolAddress((void**)&Ap, g_ATT);
    cudaGetSymbolAddress((void**)&WQp, g_WQ);
    cudaGetSymbolAddress((void**)&WKp, g_WK);
    cudaGetSymbolAddress((void**)&WVp, g_WV);
    cudaGetSymbolAddress((void**)&WOp, g_WO);

    const int gemm_smem = (2 * BM * SPAD + 2 * BN * SPAD) * 4;   // 73728 B
    const int attn_smem = (128 * 68 + 64 * 68 + 64 * 68) * 4;    // 69632 B
    static bool attr_done = false;
    if (!attr_done) {
        cudaFuncSetAttribute(gemm_tf32<1>, cudaFuncAttributeMaxDynamicSharedMemorySize, gemm_smem);
        cudaFuncSetAttribute(gemm_tf32<0>, cudaFuncAttributeMaxDynamicSharedMemorySize, gemm_smem);
        cudaFuncSetAttribute(attn_mma_kernel, cudaFuncAttributeMaxDynamicSharedMemorySize, attn_smem);
        attr_done = true;
    }

    // 0. Pre-round all weights to tf32 (idempotent, exact for GEMM)
    preround_weights<<<(WTOTAL / 4 + 255) / 256, 256>>>(
        WQ, WK, WV, WO, WQp, WKp, WVp, WOp);

    // 1. Q projection with fused RoPE (A = raw x -> cvt A)
    gemm_tf32<1><<<dim3(DMODEL / BN, MTOK / BM, 1), 256, gemm_smem>>>(
        x, WQp, WQp, Qp, Qp, MTOK, DMODEL, DMODEL, tpos, 1, 1);
    // 1b. K (fused RoPE) and V projections in one launch
    gemm_tf32<1><<<dim3((NGROUPS * DK) / BN, MTOK / BM, 2), 256, gemm_smem>>>(
        x, WKp, WVp, Kp, Vp, MTOK, NGROUPS * DK, DMODEL, tpos, 1, 0);

    // 2. Attention (R11 kernel; epilogue tf32-rounds ATT)
    attn_mma_kernel<<<dim3(TLEN / 128, NHEADS, BATCH), 256, attn_smem>>>(Qp, Kp, Vp, Ap);

    // 3. Output projection (A = pre-rounded ATT -> no cvt at all)
    gemm_tf32<0><<<dim3(DMODEL / BN, MTOK / BM, 1), 256, gemm_smem>>>(
        Ap, WOp, WOp, out, out, MTOK, DMODEL, DMODEL, tpos, 0, 0);
}